// round 1
// baseline (speedup 1.0000x reference)
#include <cuda_runtime.h>
#include <cuda_bf16.h>
#include <math.h>

// Problem constants
#define B_     16
#define T_     4096
#define KF     1024
#define DIN    512
#define DM     256
#define DOUT   256
#define NL     2
#define DS     16
#define DCONV  4
#define DI     512
#define DTR    16
#define NT     (B_*KF)   // 16384 tokens

// ---------------- scratch (device globals; no runtime alloc) ----------------
__device__ float g_x  [(size_t)NT*DM];       // residual stream
__device__ float g_xn [(size_t)NT*DM];       // layernorm output
__device__ float g_xz [(size_t)NT*2*DI];     // in-projection (xp | z)
__device__ float g_xc [(size_t)NT*DI];       // conv+silu output
__device__ float g_bc [(size_t)NT*32];       // Bm(16) | Cm(16) per token
__device__ float g_dt [(size_t)NT*DI];       // softplus(dt)
__device__ float g_y  [(size_t)NT*DI];       // scan output (gated)
__device__ float g_redp[(size_t)B_*16*DM];   // partial masked sums

// ---------------- generic fp32 GEMM: C[M,N] = A[M,Kd] * W[N,Kd]^T -----------
// optional bias[N], optional resid[M,N] added in epilogue.
// GATHER=true: A row r is features[rowoff[r]] (keyframe gather fused).
template<bool GATHER>
__global__ void gemm64_kernel(const float* __restrict__ A,
                              const float* __restrict__ W,
                              float* __restrict__ C,
                              int M, int N, int Kd,
                              const float* __restrict__ bias,
                              const float* __restrict__ resid,
                              const float* __restrict__ feats,
                              const int*   __restrict__ idx)
{
    __shared__ __align__(16) float As[16][68];
    __shared__ __align__(16) float Ws[16][68];
    __shared__ int rowoff[64];

    const int tid = threadIdx.x;        // 256 threads
    const int tx  = tid & 15;
    const int ty  = tid >> 4;
    const int row0 = blockIdx.y * 64;
    const int n0   = blockIdx.x * 64;

    if (GATHER) {
        if (tid < 64) {
            int t = row0 + tid;
            rowoff[tid] = (t / KF) * T_ + idx[t];
        }
        __syncthreads();
    }

    float acc[4][4] = {};

    for (int k0 = 0; k0 < Kd; k0 += 16) {
        #pragma unroll
        for (int i = tid; i < 64*16; i += 256) {
            int r = i >> 4;
            int c = i & 15;
            float av;
            if (GATHER)
                av = feats[(size_t)rowoff[r] * Kd + (k0 + c)];
            else
                av = A[(size_t)(row0 + r) * Kd + (k0 + c)];
            As[c][r] = av;
            Ws[c][r] = W[(size_t)(n0 + r) * Kd + (k0 + c)];
        }
        __syncthreads();

        #pragma unroll
        for (int kk = 0; kk < 16; ++kk) {
            float4 a4 = *reinterpret_cast<const float4*>(&As[kk][ty*4]);
            float4 w4 = *reinterpret_cast<const float4*>(&Ws[kk][tx*4]);
            float a[4] = {a4.x, a4.y, a4.z, a4.w};
            float w[4] = {w4.x, w4.y, w4.z, w4.w};
            #pragma unroll
            for (int i = 0; i < 4; ++i)
                #pragma unroll
                for (int j = 0; j < 4; ++j)
                    acc[i][j] += a[i] * w[j];
        }
        __syncthreads();
    }

    #pragma unroll
    for (int i = 0; i < 4; ++i) {
        int row = row0 + ty*4 + i;
        #pragma unroll
        for (int j = 0; j < 4; ++j) {
            int col = n0 + tx*4 + j;
            float v = acc[i][j];
            if (bias)  v += bias[col];
            if (resid) v += resid[(size_t)row*N + col];
            C[(size_t)row*N + col] = v;
        }
    }
}

// ---------------- LayerNorm over DM=256 (one block per token) ---------------
__global__ void ln_kernel(const float* __restrict__ x,
                          const float* __restrict__ gam,
                          const float* __restrict__ bet,
                          float* __restrict__ xn)
{
    const int t   = blockIdx.x;
    const int tid = threadIdx.x;  // 256
    float v = x[(size_t)t*DM + tid];

    __shared__ float sred[8];

    // mean
    float s = v;
    #pragma unroll
    for (int o = 16; o; o >>= 1) s += __shfl_xor_sync(0xffffffffu, s, o);
    if ((tid & 31) == 0) sred[tid >> 5] = s;
    __syncthreads();
    if (tid < 32) {
        float q = (tid < 8) ? sred[tid] : 0.f;
        #pragma unroll
        for (int o = 4; o; o >>= 1) q += __shfl_xor_sync(0xffffffffu, q, o);
        if (tid == 0) sred[0] = q;
    }
    __syncthreads();
    float mu = sred[0] * (1.0f / DM);
    __syncthreads();

    // variance
    float dv = v - mu;
    s = dv * dv;
    #pragma unroll
    for (int o = 16; o; o >>= 1) s += __shfl_xor_sync(0xffffffffu, s, o);
    if ((tid & 31) == 0) sred[tid >> 5] = s;
    __syncthreads();
    if (tid < 32) {
        float q = (tid < 8) ? sred[tid] : 0.f;
        #pragma unroll
        for (int o = 4; o; o >>= 1) q += __shfl_xor_sync(0xffffffffu, q, o);
        if (tid == 0) sred[0] = q;
    }
    __syncthreads();
    float var = sred[0] * (1.0f / DM);

    xn[(size_t)t*DM + tid] = dv * rsqrtf(var + 1e-5f) * gam[tid] + bet[tid];
}

// ---------------- causal depthwise conv (width 4) + SiLU --------------------
__global__ void conv_kernel(const float* __restrict__ xz,
                            const float* __restrict__ cw,
                            const float* __restrict__ cb,
                            float* __restrict__ xc)
{
    int gi = blockIdx.x * 256 + threadIdx.x;  // over NT*DI
    if (gi >= NT*DI) return;
    int d = gi & (DI-1);
    int t = gi >> 9;
    int k = t & (KF-1);

    float acc = cb[d];
    #pragma unroll
    for (int j = 0; j < DCONV; ++j) {
        int kk = k - (DCONV-1) + j;
        if (kk >= 0)
            acc += cw[d*DCONV + j] * xz[(size_t)(t - (DCONV-1) + j) * (2*DI) + d];
    }
    float sig = 1.0f / (1.0f + __expf(-acc));
    xc[(size_t)t*DI + d] = acc * sig;
}

// ---------------- x_dbl (48 outs) + dt = softplus(...) per token ------------
__global__ void xdbl_dt_kernel(const float* __restrict__ xc,
                               const float* __restrict__ W_xp,
                               const float* __restrict__ W_dt,
                               const float* __restrict__ b_dt,
                               float* __restrict__ bc,
                               float* __restrict__ dtout)
{
    const int t   = blockIdx.x;
    const int tid = threadIdx.x;   // 256
    __shared__ float s_xc[DI];
    __shared__ float s_dbl[48];

    s_xc[tid]       = xc[(size_t)t*DI + tid];
    s_xc[tid + 256] = xc[(size_t)t*DI + 256 + tid];
    __syncthreads();

    const int w    = tid >> 5;
    const int lane = tid & 31;
    for (int e = w; e < 48; e += 8) {
        const float* wrow = W_xp + (size_t)e * DI;
        float acc = 0.f;
        #pragma unroll 4
        for (int i = lane; i < DI; i += 32) acc += s_xc[i] * wrow[i];
        #pragma unroll
        for (int o = 16; o; o >>= 1) acc += __shfl_xor_sync(0xffffffffu, acc, o);
        if (lane == 0) s_dbl[e] = acc;
    }
    __syncthreads();

    if (tid < 32) bc[(size_t)t*32 + tid] = s_dbl[16 + tid];  // Bm | Cm

    #pragma unroll
    for (int d = tid; d < DI; d += 256) {
        float acc = b_dt[d];
        #pragma unroll
        for (int r = 0; r < DTR; ++r) acc += s_dbl[r] * W_dt[d*DTR + r];
        dtout[(size_t)t*DI + d] = (acc > 20.f) ? acc : log1pf(__expf(acc));
    }
}

// ---------------- selective scan: half-warp per (b,d), lane = state ---------
__global__ void scan_kernel(const float* __restrict__ dt,
                            const float* __restrict__ xc,
                            const float* __restrict__ bc,
                            const float* __restrict__ xz,
                            const float* __restrict__ Al,
                            const float* __restrict__ Dp,
                            float* __restrict__ y)
{
    const int warp_gid = (blockIdx.x * blockDim.x + threadIdx.x) >> 5;
    const int lane = threadIdx.x & 31;
    const int half = lane >> 4;
    const int s    = lane & 15;
    const int b    = warp_gid >> 8;              // 256 warps per batch
    const int d    = ((warp_gid & 255) << 1) + half;

    const float a  = -__expf(Al[d*DS + s]);
    const float dp = Dp[d];
    float h = 0.f;
    const size_t tbase = (size_t)b * KF;

    for (int k = 0; k < KF; ++k) {
        const size_t t = tbase + k;
        float dtv = dt[t*DI + d];
        float xcv = xc[t*DI + d];
        float bm  = bc[t*32 + s];
        float cm  = bc[t*32 + 16 + s];
        h = __expf(dtv * a) * h + dtv * bm * xcv;
        float yp = h * cm;
        yp += __shfl_xor_sync(0xffffffffu, yp, 8);
        yp += __shfl_xor_sync(0xffffffffu, yp, 4);
        yp += __shfl_xor_sync(0xffffffffu, yp, 2);
        yp += __shfl_xor_sync(0xffffffffu, yp, 1);
        if (s == 0) {
            float zv  = xz[t*(2*DI) + DI + d];
            float sig = 1.0f / (1.0f + __expf(-zv));
            y[t*DI + d] = (yp + dp * xcv) * (zv * sig);
        }
    }
}

// ---------------- masked partial reduction over K ---------------------------
__global__ void reduce_kernel(const float* __restrict__ x,
                              const unsigned char* __restrict__ mask,
                              float* __restrict__ redp)
{
    const int b  = blockIdx.x;
    const int ch = blockIdx.y;   // 16 chunks of 64
    const int m  = threadIdx.x;  // 256
    float acc = 0.f;
    const int kbeg = ch * 64;
    #pragma unroll 4
    for (int k = kbeg; k < kbeg + 64; ++k) {
        if (!mask[b*KF + k])
            acc += x[((size_t)b*KF + k)*DM + m];
    }
    redp[((size_t)b*16 + ch)*DM + m] = acc;
}

// ---------------- combine partials + output projection + mean ---------------
__global__ void final_kernel(const float* __restrict__ redp,
                             const unsigned char* __restrict__ mask,
                             const float* __restrict__ w_op,
                             const float* __restrict__ b_op,
                             float* __restrict__ out)
{
    const int b = blockIdx.x;
    const int o = threadIdx.x;   // 256
    __shared__ float s_r[DM];
    __shared__ int s_cnt;

    if (o == 0) s_cnt = 0;
    __syncthreads();

    int c = 0;
    #pragma unroll 4
    for (int k = o; k < KF; k += 256) c += mask[b*KF + k] ? 0 : 1;
    atomicAdd(&s_cnt, c);

    float acc = 0.f;
    #pragma unroll
    for (int ch = 0; ch < 16; ++ch) acc += redp[((size_t)b*16 + ch)*DM + o];
    s_r[o] = acc;
    __syncthreads();

    float cnt = fmaxf((float)s_cnt, 1.0f);
    float dot = 0.f;
    #pragma unroll 4
    for (int m = 0; m < DM; ++m) dot += s_r[m] * w_op[o*DM + m];
    out[(size_t)b*DOUT + o] = dot / cnt + b_op[o];
}

// ---------------- launch ----------------------------------------------------
extern "C" void kernel_launch(void* const* d_in, const int* in_sizes, int n_in,
                              void* d_out, int out_size)
{
    const float*         feats  = (const float*)d_in[0];
    const int*           idx    = (const int*)d_in[1];
    const unsigned char* mask   = (const unsigned char*)d_in[2];
    const float* w_ip   = (const float*)d_in[3];
    const float* b_ip   = (const float*)d_in[4];
    const float* ln_g   = (const float*)d_in[5];
    const float* ln_b   = (const float*)d_in[6];
    const float* W_in   = (const float*)d_in[7];
    const float* conv_w = (const float*)d_in[8];
    const float* conv_b = (const float*)d_in[9];
    const float* W_xp   = (const float*)d_in[10];
    const float* W_dt   = (const float*)d_in[11];
    const float* b_dt   = (const float*)d_in[12];
    const float* A_log  = (const float*)d_in[13];
    const float* Dp     = (const float*)d_in[14];
    const float* W_out  = (const float*)d_in[15];
    const float* w_op   = (const float*)d_in[16];
    const float* b_op   = (const float*)d_in[17];
    float* out = (float*)d_out;

    float *x, *xn, *xz, *xc, *bc, *dt, *y, *redp;
    cudaGetSymbolAddress((void**)&x,    g_x);
    cudaGetSymbolAddress((void**)&xn,   g_xn);
    cudaGetSymbolAddress((void**)&xz,   g_xz);
    cudaGetSymbolAddress((void**)&xc,   g_xc);
    cudaGetSymbolAddress((void**)&bc,   g_bc);
    cudaGetSymbolAddress((void**)&dt,   g_dt);
    cudaGetSymbolAddress((void**)&y,    g_y);
    cudaGetSymbolAddress((void**)&redp, g_redp);

    // input projection with fused keyframe gather: x = gather(feats) @ w_ip^T + b_ip
    gemm64_kernel<true><<<dim3(DM/64, NT/64), 256>>>(
        nullptr, w_ip, x, NT, DM, DIN, b_ip, nullptr, feats, idx);

    for (int l = 0; l < NL; ++l) {
        ln_kernel<<<NT, 256>>>(x, ln_g + l*DM, ln_b + l*DM, xn);

        gemm64_kernel<false><<<dim3(2*DI/64, NT/64), 256>>>(
            xn, W_in + (size_t)l*2*DI*DM, xz, NT, 2*DI, DM,
            nullptr, nullptr, nullptr, nullptr);

        conv_kernel<<<(NT*DI)/256, 256>>>(
            xz, conv_w + (size_t)l*DI*DCONV, conv_b + (size_t)l*DI, xc);

        xdbl_dt_kernel<<<NT, 256>>>(
            xc, W_xp + (size_t)l*(DTR+2*DS)*DI, W_dt + (size_t)l*DI*DTR,
            b_dt + (size_t)l*DI, bc, dt);

        scan_kernel<<<(B_*DI/2)/8, 256>>>(
            dt, xc, bc, xz, A_log + (size_t)l*DI*DS, Dp + (size_t)l*DI, y);

        // out projection + residual (in-place on x: each elem read-then-written by one thread)
        gemm64_kernel<false><<<dim3(DM/64, NT/64), 256>>>(
            y, W_out + (size_t)l*DM*DI, x, NT, DM, DI,
            nullptr, x, nullptr, nullptr);
    }

    reduce_kernel<<<dim3(B_, 16), 256>>>(x, mask, redp);
    final_kernel<<<B_, 256>>>(redp, mask, w_op, b_op, out);
}

// round 3
// speedup vs baseline: 2.2276x; 2.2276x over previous
#include <cuda_runtime.h>
#include <cuda_bf16.h>
#include <math.h>
#include <cstdint>

// Problem constants
#define B_     16
#define T_     4096
#define KF     1024
#define DIN    512
#define DM     256
#define DOUT   256
#define NL     2
#define DS     16
#define DCONV  4
#define DI     512
#define DTR    16
#define NT     (B_*KF)   // 16384 tokens

// ---------------- scratch (device globals; no runtime alloc) ----------------
__device__ float g_x  [(size_t)NT*DM];       // residual stream
__device__ float g_xn [(size_t)NT*DM];       // layernorm output
__device__ float g_xz [(size_t)NT*2*DI];     // in-projection (xp | z)
__device__ float g_xc [(size_t)NT*DI];       // conv+silu output
__device__ float g_zs [(size_t)NT*DI];       // z * silu(z)... actually silu(z)
__device__ float g_dbl[(size_t)NT*48];       // dt_low(16) | Bm(16) | Cm(16)
__device__ float g_dt [(size_t)NT*DI];       // softplus(dt)
__device__ float g_y  [(size_t)NT*DI];       // scan output (gated)
__device__ float g_redp[(size_t)B_*16*DM];   // partial masked sums

// ---------------------------- helpers ---------------------------------------
__device__ __forceinline__ uint32_t f32_to_tf32(float f) {
    uint32_t r;
    asm("cvt.rna.tf32.f32 %0, %1;" : "=r"(r) : "f"(f));
    return r;
}

__device__ __forceinline__ void mma_tf32(float* d, const uint32_t* a,
                                         const uint32_t* b) {
    asm volatile(
        "mma.sync.aligned.m16n8k8.row.col.f32.tf32.tf32.f32 "
        "{%0,%1,%2,%3}, {%4,%5,%6,%7}, {%8,%9}, {%0,%1,%2,%3};"
        : "+f"(d[0]), "+f"(d[1]), "+f"(d[2]), "+f"(d[3])
        : "r"(a[0]), "r"(a[1]), "r"(a[2]), "r"(a[3]),
          "r"(b[0]), "r"(b[1]));
}

// =================== mma.sync tf32 GEMM: C = A @ W^T ========================
// CTA tile: 128 (M) x NTILE (N). 8 warps arranged (8/WN) x WN.
// K chunked by 32 floats, double-buffered smem (padded stride 36).
// GATHER: A row r = features[rowoff[r]]. BIAS adds bias[n]. RESID adds
// resid[m,n] (may alias C). OP==1 applies softplus.
template<int NTILE, int WN, bool GATHER, bool BIAS, bool RESID, int OP>
__global__ __launch_bounds__(256)
void gemm_mma(const float* __restrict__ A, const float* __restrict__ W,
              float* __restrict__ C, int N, int Kd,
              const float* __restrict__ bias, const float* __restrict__ resid,
              const float* __restrict__ feats, const int* __restrict__ idx)
{
    constexpr int WM   = 8 / WN;
    constexpr int RM   = 128 / WM;       // rows per warp tile
    constexpr int RN   = NTILE / WN;     // cols per warp tile
    constexpr int mM   = RM / 16;
    constexpr int mN   = RN / 8;
    constexpr int SA   = 36;             // padded f32 stride
    constexpr int ABUF = 128 * SA;
    constexpr int BBUF = NTILE * SA;
    constexpr int BL   = (NTILE * 8 + 255) / 256;

    extern __shared__ float sm[];
    float* sA = sm;              // [2][128][SA]
    float* sB = sm + 2 * ABUF;   // [2][NTILE][SA]
    __shared__ int rowoff[128];

    const int tid  = threadIdx.x;
    const int warp = tid >> 5, lane = tid & 31;
    const int gid  = lane >> 2, tig = lane & 3;
    const int wm   = warp % WM, wn = warp / WM;
    const int m0   = blockIdx.y * 128, n0 = blockIdx.x * NTILE;

    if (GATHER) {
        if (tid < 128) {
            int t = m0 + tid;
            rowoff[tid] = (t >> 10) * T_ + idx[t];
        }
        __syncthreads();
    }

    float acc[mM][mN][4];
    #pragma unroll
    for (int i = 0; i < mM; ++i)
        #pragma unroll
        for (int j = 0; j < mN; ++j)
            #pragma unroll
            for (int q = 0; q < 4; ++q) acc[i][j][q] = 0.f;

    float4 ar[4];
    float4 br[BL];

    auto ldA = [&](int k0) {
        #pragma unroll
        for (int j = 0; j < 4; ++j) {
            int it = tid + 256 * j;
            int r = it >> 3, q = it & 7;
            const float* p = GATHER
                ? feats + (size_t)rowoff[r] * Kd + k0 + q * 4
                : A + (size_t)(m0 + r) * Kd + k0 + q * 4;
            ar[j] = *reinterpret_cast<const float4*>(p);
        }
    };
    auto ldB = [&](int k0) {
        #pragma unroll
        for (int j = 0; j < BL; ++j) {
            int it = tid + 256 * j;
            if ((NTILE * 8 % 256 == 0) || it < NTILE * 8) {
                int r = it >> 3, q = it & 7;
                br[j] = *reinterpret_cast<const float4*>(
                    W + (size_t)(n0 + r) * Kd + k0 + q * 4);
            }
        }
    };
    auto stA = [&](int buf) {
        #pragma unroll
        for (int j = 0; j < 4; ++j) {
            int it = tid + 256 * j;
            int r = it >> 3, q = it & 7;
            float4 t4;
            t4.x = __uint_as_float(f32_to_tf32(ar[j].x));
            t4.y = __uint_as_float(f32_to_tf32(ar[j].y));
            t4.z = __uint_as_float(f32_to_tf32(ar[j].z));
            t4.w = __uint_as_float(f32_to_tf32(ar[j].w));
            *reinterpret_cast<float4*>(&sA[buf * ABUF + r * SA + q * 4]) = t4;
        }
    };
    auto stB = [&](int buf) {
        #pragma unroll
        for (int j = 0; j < BL; ++j) {
            int it = tid + 256 * j;
            if ((NTILE * 8 % 256 == 0) || it < NTILE * 8) {
                int r = it >> 3, q = it & 7;
                float4 t4;
                t4.x = __uint_as_float(f32_to_tf32(br[j].x));
                t4.y = __uint_as_float(f32_to_tf32(br[j].y));
                t4.z = __uint_as_float(f32_to_tf32(br[j].z));
                t4.w = __uint_as_float(f32_to_tf32(br[j].w));
                *reinterpret_cast<float4*>(&sB[buf * BBUF + r * SA + q * 4]) = t4;
            }
        }
    };

    const int nc = Kd >> 5;
    ldA(0); ldB(0);
    stA(0); stB(0);
    __syncthreads();

    for (int i = 0; i < nc; ++i) {
        const int buf = i & 1;
        if (i + 1 < nc) { ldA((i + 1) << 5); ldB((i + 1) << 5); }

        const float* bA = sA + buf * ABUF;
        const float* bB = sB + buf * BBUF;
        #pragma unroll
        for (int kk = 0; kk < 32; kk += 8) {
            uint32_t afr[mM][4];
            #pragma unroll
            for (int i2 = 0; i2 < mM; ++i2) {
                int rb = wm * RM + i2 * 16;
                afr[i2][0] = __float_as_uint(bA[(rb + gid)     * SA + kk + tig]);
                afr[i2][1] = __float_as_uint(bA[(rb + 8 + gid) * SA + kk + tig]);
                afr[i2][2] = __float_as_uint(bA[(rb + gid)     * SA + kk + tig + 4]);
                afr[i2][3] = __float_as_uint(bA[(rb + 8 + gid) * SA + kk + tig + 4]);
            }
            uint32_t bfr[mN][2];
            #pragma unroll
            for (int j2 = 0; j2 < mN; ++j2) {
                int cb = wn * RN + j2 * 8;
                bfr[j2][0] = __float_as_uint(bB[(cb + gid) * SA + kk + tig]);
                bfr[j2][1] = __float_as_uint(bB[(cb + gid) * SA + kk + tig + 4]);
            }
            #pragma unroll
            for (int i2 = 0; i2 < mM; ++i2)
                #pragma unroll
                for (int j2 = 0; j2 < mN; ++j2)
                    mma_tf32(acc[i2][j2], afr[i2], bfr[j2]);
        }

        if (i + 1 < nc) { stA(buf ^ 1); stB(buf ^ 1); __syncthreads(); }
    }

    // epilogue
    #pragma unroll
    for (int i2 = 0; i2 < mM; ++i2) {
        #pragma unroll
        for (int j2 = 0; j2 < mN; ++j2) {
            int row = m0 + wm * RM + i2 * 16 + gid;
            int col = n0 + wn * RN + j2 * 8 + tig * 2;
            float v0 = acc[i2][j2][0], v1 = acc[i2][j2][1];
            float v2 = acc[i2][j2][2], v3 = acc[i2][j2][3];
            if (BIAS) {
                float bc0 = bias[col], bc1 = bias[col + 1];
                v0 += bc0; v1 += bc1; v2 += bc0; v3 += bc1;
            }
            if (RESID) {
                v0 += resid[(size_t)row * N + col];
                v1 += resid[(size_t)row * N + col + 1];
                v2 += resid[(size_t)(row + 8) * N + col];
                v3 += resid[(size_t)(row + 8) * N + col + 1];
            }
            if (OP == 1) {
                v0 = (v0 > 20.f) ? v0 : log1pf(__expf(v0));
                v1 = (v1 > 20.f) ? v1 : log1pf(__expf(v1));
                v2 = (v2 > 20.f) ? v2 : log1pf(__expf(v2));
                v3 = (v3 > 20.f) ? v3 : log1pf(__expf(v3));
            }
            *reinterpret_cast<float2*>(&C[(size_t)row * N + col]) =
                make_float2(v0, v1);
            *reinterpret_cast<float2*>(&C[(size_t)(row + 8) * N + col]) =
                make_float2(v2, v3);
        }
    }
}

// ---------------- LayerNorm over DM=256 (one block per token) ---------------
__global__ void ln_kernel(const float* __restrict__ x,
                          const float* __restrict__ gam,
                          const float* __restrict__ bet,
                          float* __restrict__ xn)
{
    const int t   = blockIdx.x;
    const int tid = threadIdx.x;  // 256
    float v = x[(size_t)t*DM + tid];

    __shared__ float sred[8];

    float s = v;
    #pragma unroll
    for (int o = 16; o; o >>= 1) s += __shfl_xor_sync(0xffffffffu, s, o);
    if ((tid & 31) == 0) sred[tid >> 5] = s;
    __syncthreads();
    if (tid < 32) {
        float q = (tid < 8) ? sred[tid] : 0.f;
        #pragma unroll
        for (int o = 4; o; o >>= 1) q += __shfl_xor_sync(0xffffffffu, q, o);
        if (tid == 0) sred[0] = q;
    }
    __syncthreads();
    float mu = sred[0] * (1.0f / DM);
    __syncthreads();

    float dv = v - mu;
    s = dv * dv;
    #pragma unroll
    for (int o = 16; o; o >>= 1) s += __shfl_xor_sync(0xffffffffu, s, o);
    if ((tid & 31) == 0) sred[tid >> 5] = s;
    __syncthreads();
    if (tid < 32) {
        float q = (tid < 8) ? sred[tid] : 0.f;
        #pragma unroll
        for (int o = 4; o; o >>= 1) q += __shfl_xor_sync(0xffffffffu, q, o);
        if (tid == 0) sred[0] = q;
    }
    __syncthreads();
    float var = sred[0] * (1.0f / DM);

    xn[(size_t)t*DM + tid] = dv * rsqrtf(var + 1e-5f) * gam[tid] + bet[tid];
}

// ------- causal depthwise conv (width 4) + SiLU, plus z*silu(z) --------------
__global__ void conv_zs_kernel(const float* __restrict__ xz,
                               const float* __restrict__ cw,
                               const float* __restrict__ cb,
                               float* __restrict__ xc,
                               float* __restrict__ zs)
{
    int gi = blockIdx.x * 256 + threadIdx.x;  // over NT*DI
    if (gi >= NT*DI) return;
    int d = gi & (DI-1);
    int t = gi >> 9;
    int k = t & (KF-1);

    float acc = cb[d];
    #pragma unroll
    for (int j = 0; j < DCONV; ++j) {
        int kk = k - (DCONV-1) + j;
        if (kk >= 0)
            acc += cw[d*DCONV + j] * xz[(size_t)(t - (DCONV-1) + j) * (2*DI) + d];
    }
    float sig = 1.0f / (1.0f + __expf(-acc));
    xc[(size_t)t*DI + d] = acc * sig;

    float zv = xz[(size_t)t * (2*DI) + DI + d];
    float zsig = 1.0f / (1.0f + __expf(-zv));
    zs[(size_t)t*DI + d] = zv * zsig;
}

// ------- dt = softplus(dbl[:, :16] @ W_dt^T + b_dt), W_dt reg-cached ---------
__global__ void dt_kernel(const float* __restrict__ dbl,
                          const float* __restrict__ Wdt,
                          const float* __restrict__ bdt,
                          float* __restrict__ dtout)
{
    __shared__ float s_dbl[64 * 16];
    const int tid = threadIdx.x;      // 256
    const int t0  = blockIdx.x * 64;

    float w0[16], w1[16];
    #pragma unroll
    for (int r = 0; r < 16; ++r) {
        w0[r] = Wdt[tid * 16 + r];
        w1[r] = Wdt[(tid + 256) * 16 + r];
    }
    const float b0 = bdt[tid], b1 = bdt[tid + 256];

    for (int i = tid; i < 64 * 16; i += 256) {
        int tt = i >> 4, r = i & 15;
        s_dbl[i] = dbl[(size_t)(t0 + tt) * 48 + r];
    }
    __syncthreads();

    for (int tt = 0; tt < 64; ++tt) {
        float a0 = b0, a1 = b1;
        #pragma unroll
        for (int r = 0; r < 16; ++r) {
            float v = s_dbl[tt * 16 + r];
            a0 += v * w0[r];
            a1 += v * w1[r];
        }
        size_t t = (size_t)(t0 + tt) * DI;
        dtout[t + tid]       = (a0 > 20.f) ? a0 : log1pf(__expf(a0));
        dtout[t + tid + 256] = (a1 > 20.f) ? a1 : log1pf(__expf(a1));
    }
}

// ---------------- selective scan: half-warp per (b,d), lane = state ---------
__global__ void scan_kernel(const float* __restrict__ dt,
                            const float* __restrict__ xc,
                            const float* __restrict__ dbl,
                            const float* __restrict__ zs,
                            const float* __restrict__ Al,
                            const float* __restrict__ Dp,
                            float* __restrict__ y)
{
    const int warp_gid = (blockIdx.x * blockDim.x + threadIdx.x) >> 5;
    const int lane = threadIdx.x & 31;
    const int half = lane >> 4;
    const int s    = lane & 15;
    const int b    = warp_gid >> 8;
    const int d    = ((warp_gid & 255) << 1) + half;

    const float a  = -__expf(Al[d*DS + s]);
    const float dp = Dp[d];
    float h = 0.f;
    const size_t tbase = (size_t)b * KF;

    for (int k = 0; k < KF; ++k) {
        const size_t t = tbase + k;
        float dtv = dt[t*DI + d];
        float xcv = xc[t*DI + d];
        float bm  = dbl[t*48 + 16 + s];
        float cm  = dbl[t*48 + 32 + s];
        h = __expf(dtv * a) * h + dtv * bm * xcv;
        float yp = h * cm;
        yp += __shfl_xor_sync(0xffffffffu, yp, 8);
        yp += __shfl_xor_sync(0xffffffffu, yp, 4);
        yp += __shfl_xor_sync(0xffffffffu, yp, 2);
        yp += __shfl_xor_sync(0xffffffffu, yp, 1);
        if (s == 0) {
            y[t*DI + d] = (yp + dp * xcv) * zs[t*DI + d];
        }
    }
}

// ---------------- masked partial reduction over K ---------------------------
__global__ void reduce_kernel(const float* __restrict__ x,
                              const unsigned char* __restrict__ mask,
                              float* __restrict__ redp)
{
    const int b  = blockIdx.x;
    const int ch = blockIdx.y;
    const int m  = threadIdx.x;
    float acc = 0.f;
    const int kbeg = ch * 64;
    #pragma unroll 4
    for (int k = kbeg; k < kbeg + 64; ++k) {
        if (!mask[b*KF + k])
            acc += x[((size_t)b*KF + k)*DM + m];
    }
    redp[((size_t)b*16 + ch)*DM + m] = acc;
}

// ---------------- combine partials + output projection + mean ---------------
__global__ void final_kernel(const float* __restrict__ redp,
                             const unsigned char* __restrict__ mask,
                             const float* __restrict__ w_op,
                             const float* __restrict__ b_op,
                             float* __restrict__ out)
{
    const int b = blockIdx.x;
    const int o = threadIdx.x;
    __shared__ float s_r[DM];
    __shared__ int s_cnt;

    if (o == 0) s_cnt = 0;
    __syncthreads();

    int c = 0;
    #pragma unroll 4
    for (int k = o; k < KF; k += 256) c += mask[b*KF + k] ? 0 : 1;
    atomicAdd(&s_cnt, c);

    float acc = 0.f;
    #pragma unroll
    for (int ch = 0; ch < 16; ++ch) acc += redp[((size_t)b*16 + ch)*DM + o];
    s_r[o] = acc;
    __syncthreads();

    float cnt = fmaxf((float)s_cnt, 1.0f);
    float dot = 0.f;
    #pragma unroll 4
    for (int m = 0; m < DM; ++m) dot += s_r[m] * w_op[o*DM + m];
    out[(size_t)b*DOUT + o] = dot / cnt + b_op[o];
}

// ---------------- launch ----------------------------------------------------
extern "C" void kernel_launch(void* const* d_in, const int* in_sizes, int n_in,
                              void* d_out, int out_size)
{
    const float*         feats  = (const float*)d_in[0];
    const int*           idx    = (const int*)d_in[1];
    const unsigned char* mask   = (const unsigned char*)d_in[2];
    const float* w_ip   = (const float*)d_in[3];
    const float* b_ip   = (const float*)d_in[4];
    const float* ln_g   = (const float*)d_in[5];
    const float* ln_b   = (const float*)d_in[6];
    const float* W_in   = (const float*)d_in[7];
    const float* conv_w = (const float*)d_in[8];
    const float* conv_b = (const float*)d_in[9];
    const float* W_xp   = (const float*)d_in[10];
    const float* W_dt   = (const float*)d_in[11];
    const float* b_dt   = (const float*)d_in[12];
    const float* A_log  = (const float*)d_in[13];
    const float* Dp     = (const float*)d_in[14];
    const float* W_out  = (const float*)d_in[15];
    const float* w_op   = (const float*)d_in[16];
    const float* b_op   = (const float*)d_in[17];
    float* out = (float*)d_out;

    float *x, *xn, *xz, *xc, *zs, *dbl, *dt, *y, *redp;
    cudaGetSymbolAddress((void**)&x,    g_x);
    cudaGetSymbolAddress((void**)&xn,   g_xn);
    cudaGetSymbolAddress((void**)&xz,   g_xz);
    cudaGetSymbolAddress((void**)&xc,   g_xc);
    cudaGetSymbolAddress((void**)&zs,   g_zs);
    cudaGetSymbolAddress((void**)&dbl,  g_dbl);
    cudaGetSymbolAddress((void**)&dt,   g_dt);
    cudaGetSymbolAddress((void**)&y,    g_y);
    cudaGetSymbolAddress((void**)&redp, g_redp);

    // dynamic smem sizes: 2*(128*36) + 2*(NTILE*36) floats
    const int SM64 = (2*128*36 + 2*64*36) * 4;   // 55296
    const int SM48 = (2*128*36 + 2*48*36) * 4;   // 50688

    cudaFuncSetAttribute(gemm_mma<64, 2, true,  true,  false, 0>,
        cudaFuncAttributeMaxDynamicSharedMemorySize, SM64);
    cudaFuncSetAttribute(gemm_mma<64, 2, false, false, false, 0>,
        cudaFuncAttributeMaxDynamicSharedMemorySize, SM64);
    cudaFuncSetAttribute(gemm_mma<48, 1, false, false, false, 0>,
        cudaFuncAttributeMaxDynamicSharedMemorySize, SM48);
    cudaFuncSetAttribute(gemm_mma<64, 2, false, false, true,  0>,
        cudaFuncAttributeMaxDynamicSharedMemorySize, SM64);

    // input projection with fused keyframe gather: x = gather(feats)@w_ip^T + b
    gemm_mma<64, 2, true, true, false, 0><<<dim3(DM/64, NT/128), 256, SM64>>>(
        nullptr, w_ip, x, DM, DIN, b_ip, nullptr, feats, idx);

    for (int l = 0; l < NL; ++l) {
        ln_kernel<<<NT, 256>>>(x, ln_g + l*DM, ln_b + l*DM, xn);

        // xz = xn @ W_in^T
        gemm_mma<64, 2, false, false, false, 0>
            <<<dim3(2*DI/64, NT/128), 256, SM64>>>(
            xn, W_in + (size_t)l*2*DI*DM, xz, 2*DI, DM,
            nullptr, nullptr, nullptr, nullptr);

        conv_zs_kernel<<<(NT*DI)/256, 256>>>(
            xz, conv_w + (size_t)l*DI*DCONV, conv_b + (size_t)l*DI, xc, zs);

        // dbl = xc @ W_xp^T  (dt_low | Bm | Cm), N=48
        gemm_mma<48, 1, false, false, false, 0>
            <<<dim3(1, NT/128), 256, SM48>>>(
            xc, W_xp + (size_t)l*(DTR+2*DS)*DI, dbl, 48, DI,
            nullptr, nullptr, nullptr, nullptr);

        // dt = softplus(dbl[:, :16] @ W_dt^T + b_dt)
        dt_kernel<<<NT/64, 256>>>(
            dbl, W_dt + (size_t)l*DI*DTR, b_dt + (size_t)l*DI, dt);

        scan_kernel<<<(B_*DI/2)/8, 256>>>(
            dt, xc, dbl, zs, A_log + (size_t)l*DI*DS, Dp + (size_t)l*DI, y);

        // x = y @ W_out^T + x   (residual, in-place safe: one thread per elem)
        gemm_mma<64, 2, false, false, true, 0>
            <<<dim3(DM/64, NT/128), 256, SM64>>>(
            y, W_out + (size_t)l*DM*DI, x, DM, DI,
            nullptr, x, nullptr, nullptr);
    }

    reduce_kernel<<<dim3(B_, 16), 256>>>(x, mask, redp);
    final_kernel<<<B_, 256>>>(redp, mask, w_op, b_op, out);
}

// round 4
// speedup vs baseline: 2.2760x; 1.0218x over previous
#include <cuda_runtime.h>
#include <cuda_bf16.h>
#include <math.h>
#include <cstdint>

// Problem constants
#define B_     16
#define T_     4096
#define KF     1024
#define DIN    512
#define DM     256
#define DOUT   256
#define NL     2
#define DS     16
#define DCONV  4
#define DI     512
#define DTR    16
#define NT     (B_*KF)   // 16384 tokens

// ---------------- scratch (device globals; no runtime alloc) ----------------
__device__ float g_x  [(size_t)NT*DM];       // residual stream
__device__ float g_xn [(size_t)NT*DM];       // layernorm output
__device__ float g_xz [(size_t)NT*2*DI];     // in-projection (xp | z)
__device__ float g_xc [(size_t)NT*DI];       // conv+silu output
__device__ float g_zs [(size_t)NT*DI];       // z*silu(z)
__device__ float g_dbl[(size_t)NT*48];       // dt_low(16) | Bm(16) | Cm(16)
__device__ float g_dt [(size_t)NT*DI];       // softplus(dt)
__device__ float g_y  [(size_t)NT*DI];       // scan output (gated)
__device__ float g_redp[(size_t)B_*16*DM];   // partial masked sums

// ---------------------------- helpers ---------------------------------------
__device__ __forceinline__ uint32_t f32_to_tf32(float f) {
    uint32_t r;
    asm("cvt.rna.tf32.f32 %0, %1;" : "=r"(r) : "f"(f));
    return r;
}

__device__ __forceinline__ void mma_tf32(float* d, const uint32_t* a,
                                         const uint32_t* b) {
    asm volatile(
        "mma.sync.aligned.m16n8k8.row.col.f32.tf32.tf32.f32 "
        "{%0,%1,%2,%3}, {%4,%5,%6,%7}, {%8,%9}, {%0,%1,%2,%3};"
        : "+f"(d[0]), "+f"(d[1]), "+f"(d[2]), "+f"(d[3])
        : "r"(a[0]), "r"(a[1]), "r"(a[2]), "r"(a[3]),
          "r"(b[0]), "r"(b[1]));
}

#define CP_ASYNC16(smem_u32, gptr) \
    asm volatile("cp.async.ca.shared.global [%0], [%1], 16;" \
        :: "r"(smem_u32), "l"(gptr))
#define CP_COMMIT() asm volatile("cp.async.commit_group;")
#define CP_WAIT(n)  asm volatile("cp.async.wait_group %0;" :: "n"(n))

// =================== cp.async pipelined tf32 GEMM: C = A @ W^T ==============
// CTA tile 128 x NTILE, 8 warps (8/WN x WN), K chunked by 32 f32, 3 stages.
template<int NTILE, int WN, bool GATHER, bool BIAS, bool RESID>
__global__ __launch_bounds__(256)
void gemm_cp(const float* __restrict__ A, const float* __restrict__ W,
             float* __restrict__ C, int N, int Kd,
             const float* __restrict__ bias, const float* __restrict__ resid,
             const float* __restrict__ feats, const int* __restrict__ idx)
{
    constexpr int STAGES = 3;
    constexpr int WM   = 8 / WN;
    constexpr int RM   = 128 / WM;
    constexpr int RN   = NTILE / WN;
    constexpr int mM   = RM / 16;
    constexpr int mN   = RN / 8;
    constexpr int SA   = 36;             // padded f32 stride (144B rows)
    constexpr int ABUF = 128 * SA;
    constexpr int BBUF = NTILE * SA;
    constexpr int BL   = (NTILE * 8 + 255) / 256;

    extern __shared__ float sm[];
    float* sA = sm;                      // [STAGES][128][SA]
    float* sB = sm + STAGES * ABUF;      // [STAGES][NTILE][SA]
    __shared__ int rowoff[128];

    const int tid  = threadIdx.x;
    const int warp = tid >> 5, lane = tid & 31;
    const int gid  = lane >> 2, tig = lane & 3;
    const int wm   = warp % WM, wn = warp / WM;
    const int m0   = blockIdx.y * 128, n0 = blockIdx.x * NTILE;

    if (GATHER) {
        if (tid < 128) {
            int t = m0 + tid;
            rowoff[tid] = (t >> 10) * T_ + idx[t];
        }
        __syncthreads();
    }

    const uint32_t sAu = (uint32_t)__cvta_generic_to_shared(sA);
    const uint32_t sBu = (uint32_t)__cvta_generic_to_shared(sB);

    auto issue_load = [&](int stage, int k0) {
        const uint32_t as = sAu + (uint32_t)stage * ABUF * 4;
        const uint32_t bs = sBu + (uint32_t)stage * BBUF * 4;
        #pragma unroll
        for (int j = 0; j < 4; ++j) {
            int it = tid + 256 * j;
            int r = it >> 3, q = it & 7;
            const float* p = GATHER
                ? feats + (size_t)rowoff[r] * Kd + k0 + q * 4
                : A + (size_t)(m0 + r) * Kd + k0 + q * 4;
            CP_ASYNC16(as + (uint32_t)(r * SA + q * 4) * 4, p);
        }
        #pragma unroll
        for (int j = 0; j < BL; ++j) {
            int it = tid + 256 * j;
            if ((NTILE * 8 % 256 == 0) || it < NTILE * 8) {
                int r = it >> 3, q = it & 7;
                CP_ASYNC16(bs + (uint32_t)(r * SA + q * 4) * 4,
                           W + (size_t)(n0 + r) * Kd + k0 + q * 4);
            }
        }
    };

    float acc[mM][mN][4];
    #pragma unroll
    for (int i = 0; i < mM; ++i)
        #pragma unroll
        for (int j = 0; j < mN; ++j)
            #pragma unroll
            for (int q = 0; q < 4; ++q) acc[i][j][q] = 0.f;

    const int nc = Kd >> 5;

    // prologue: prefetch STAGES-1 chunks
    #pragma unroll
    for (int s = 0; s < STAGES - 1; ++s) {
        if (s < nc) issue_load(s, s << 5);
        CP_COMMIT();
    }

    for (int i = 0; i < nc; ++i) {
        CP_WAIT(STAGES - 2);
        __syncthreads();

        const int pre = i + STAGES - 1;
        if (pre < nc) issue_load(pre % STAGES, pre << 5);
        CP_COMMIT();

        const float* bA = sA + (i % STAGES) * ABUF;
        const float* bB = sB + (i % STAGES) * BBUF;
        #pragma unroll
        for (int kk = 0; kk < 32; kk += 8) {
            uint32_t afr[mM][4];
            #pragma unroll
            for (int i2 = 0; i2 < mM; ++i2) {
                int rb = wm * RM + i2 * 16;
                afr[i2][0] = f32_to_tf32(bA[(rb + gid)     * SA + kk + tig]);
                afr[i2][1] = f32_to_tf32(bA[(rb + 8 + gid) * SA + kk + tig]);
                afr[i2][2] = f32_to_tf32(bA[(rb + gid)     * SA + kk + tig + 4]);
                afr[i2][3] = f32_to_tf32(bA[(rb + 8 + gid) * SA + kk + tig + 4]);
            }
            uint32_t bfr[mN][2];
            #pragma unroll
            for (int j2 = 0; j2 < mN; ++j2) {
                int cb = wn * RN + j2 * 8;
                bfr[j2][0] = f32_to_tf32(bB[(cb + gid) * SA + kk + tig]);
                bfr[j2][1] = f32_to_tf32(bB[(cb + gid) * SA + kk + tig + 4]);
            }
            #pragma unroll
            for (int i2 = 0; i2 < mM; ++i2)
                #pragma unroll
                for (int j2 = 0; j2 < mN; ++j2)
                    mma_tf32(acc[i2][j2], afr[i2], bfr[j2]);
        }
    }

    // epilogue
    #pragma unroll
    for (int i2 = 0; i2 < mM; ++i2) {
        #pragma unroll
        for (int j2 = 0; j2 < mN; ++j2) {
            int row = m0 + wm * RM + i2 * 16 + gid;
            int col = n0 + wn * RN + j2 * 8 + tig * 2;
            float v0 = acc[i2][j2][0], v1 = acc[i2][j2][1];
            float v2 = acc[i2][j2][2], v3 = acc[i2][j2][3];
            if (BIAS) {
                float bc0 = bias[col], bc1 = bias[col + 1];
                v0 += bc0; v1 += bc1; v2 += bc0; v3 += bc1;
            }
            if (RESID) {
                v0 += resid[(size_t)row * N + col];
                v1 += resid[(size_t)row * N + col + 1];
                v2 += resid[(size_t)(row + 8) * N + col];
                v3 += resid[(size_t)(row + 8) * N + col + 1];
            }
            *reinterpret_cast<float2*>(&C[(size_t)row * N + col]) =
                make_float2(v0, v1);
            *reinterpret_cast<float2*>(&C[(size_t)(row + 8) * N + col]) =
                make_float2(v2, v3);
        }
    }
}

// ---------------- LayerNorm over DM=256 (one block per token) ---------------
__global__ void ln_kernel(const float* __restrict__ x,
                          const float* __restrict__ gam,
                          const float* __restrict__ bet,
                          float* __restrict__ xn)
{
    const int t   = blockIdx.x;
    const int tid = threadIdx.x;  // 256
    float v = x[(size_t)t*DM + tid];

    __shared__ float sred[8];

    float s = v;
    #pragma unroll
    for (int o = 16; o; o >>= 1) s += __shfl_xor_sync(0xffffffffu, s, o);
    if ((tid & 31) == 0) sred[tid >> 5] = s;
    __syncthreads();
    if (tid < 32) {
        float q = (tid < 8) ? sred[tid] : 0.f;
        #pragma unroll
        for (int o = 4; o; o >>= 1) q += __shfl_xor_sync(0xffffffffu, q, o);
        if (tid == 0) sred[0] = q;
    }
    __syncthreads();
    float mu = sred[0] * (1.0f / DM);
    __syncthreads();

    float dv = v - mu;
    s = dv * dv;
    #pragma unroll
    for (int o = 16; o; o >>= 1) s += __shfl_xor_sync(0xffffffffu, s, o);
    if ((tid & 31) == 0) sred[tid >> 5] = s;
    __syncthreads();
    if (tid < 32) {
        float q = (tid < 8) ? sred[tid] : 0.f;
        #pragma unroll
        for (int o = 4; o; o >>= 1) q += __shfl_xor_sync(0xffffffffu, q, o);
        if (tid == 0) sred[0] = q;
    }
    __syncthreads();
    float var = sred[0] * (1.0f / DM);

    xn[(size_t)t*DM + tid] = dv * rsqrtf(var + 1e-5f) * gam[tid] + bet[tid];
}

// ------- causal depthwise conv (width 4) + SiLU + z*silu(z), float4 ---------
__global__ void conv_zs_kernel(const float* __restrict__ xz,
                               const float* __restrict__ cw,
                               const float* __restrict__ cb,
                               float* __restrict__ xc,
                               float* __restrict__ zs)
{
    int gi = blockIdx.x * 256 + threadIdx.x;  // over NT*DI/4
    if (gi >= NT*DI/4) return;
    int d4 = (gi & 127) << 2;      // d base (multiple of 4)
    int t  = gi >> 7;
    int k  = t & (KF-1);

    float4 acc = *reinterpret_cast<const float4*>(cb + d4);
    // weights for 4 channels: cw[(d4+c)*4 + j]
    float4 w0 = *reinterpret_cast<const float4*>(cw + (d4+0)*4);
    float4 w1 = *reinterpret_cast<const float4*>(cw + (d4+1)*4);
    float4 w2 = *reinterpret_cast<const float4*>(cw + (d4+2)*4);
    float4 w3 = *reinterpret_cast<const float4*>(cw + (d4+3)*4);
    const float wj[4][4] = {
        {w0.x, w1.x, w2.x, w3.x},
        {w0.y, w1.y, w2.y, w3.y},
        {w0.z, w1.z, w2.z, w3.z},
        {w0.w, w1.w, w2.w, w3.w}};

    #pragma unroll
    for (int j = 0; j < DCONV; ++j) {
        int kk = k - (DCONV-1) + j;
        if (kk >= 0) {
            float4 v = *reinterpret_cast<const float4*>(
                xz + (size_t)(t - (DCONV-1) + j) * (2*DI) + d4);
            acc.x += wj[j][0] * v.x;
            acc.y += wj[j][1] * v.y;
            acc.z += wj[j][2] * v.z;
            acc.w += wj[j][3] * v.w;
        }
    }
    float4 o;
    o.x = acc.x / (1.0f + __expf(-acc.x));
    o.y = acc.y / (1.0f + __expf(-acc.y));
    o.z = acc.z / (1.0f + __expf(-acc.z));
    o.w = acc.w / (1.0f + __expf(-acc.w));
    *reinterpret_cast<float4*>(xc + (size_t)t*DI + d4) = o;

    float4 z = *reinterpret_cast<const float4*>(
        xz + (size_t)t * (2*DI) + DI + d4);
    float4 g;
    g.x = z.x / (1.0f + __expf(-z.x));
    g.y = z.y / (1.0f + __expf(-z.y));
    g.z = z.z / (1.0f + __expf(-z.z));
    g.w = z.w / (1.0f + __expf(-z.w));
    *reinterpret_cast<float4*>(zs + (size_t)t*DI + d4) = g;
}

// ------- dt = softplus(dbl[:, :16] @ W_dt^T + b_dt), W_dt reg-cached ---------
__global__ void dt_kernel(const float* __restrict__ dbl,
                          const float* __restrict__ Wdt,
                          const float* __restrict__ bdt,
                          float* __restrict__ dtout)
{
    __shared__ float s_dbl[64 * 16];
    const int tid = threadIdx.x;      // 256
    const int t0  = blockIdx.x * 64;

    float w0[16], w1[16];
    #pragma unroll
    for (int r = 0; r < 16; ++r) {
        w0[r] = Wdt[tid * 16 + r];
        w1[r] = Wdt[(tid + 256) * 16 + r];
    }
    const float b0 = bdt[tid], b1 = bdt[tid + 256];

    for (int i = tid; i < 64 * 16; i += 256) {
        int tt = i >> 4, r = i & 15;
        s_dbl[i] = dbl[(size_t)(t0 + tt) * 48 + r];
    }
    __syncthreads();

    for (int tt = 0; tt < 64; ++tt) {
        float a0 = b0, a1 = b1;
        #pragma unroll
        for (int r = 0; r < 16; ++r) {
            float v = s_dbl[tt * 16 + r];
            a0 += v * w0[r];
            a1 += v * w1[r];
        }
        size_t t = (size_t)(t0 + tt) * DI;
        dtout[t + tid]       = (a0 > 20.f) ? a0 : __logf(1.f + __expf(a0));
        dtout[t + tid + 256] = (a1 > 20.f) ? a1 : __logf(1.f + __expf(a1));
    }
}

// ---------------- selective scan: half-warp per (b,d), lane = state ---------
__global__ void scan_kernel(const float* __restrict__ dt,
                            const float* __restrict__ xc,
                            const float* __restrict__ dbl,
                            const float* __restrict__ zs,
                            const float* __restrict__ Al,
                            const float* __restrict__ Dp,
                            float* __restrict__ y)
{
    const int warp_gid = (blockIdx.x * blockDim.x + threadIdx.x) >> 5;
    const int lane = threadIdx.x & 31;
    const int half = lane >> 4;
    const int s    = lane & 15;
    const int b    = warp_gid >> 8;
    const int d    = ((warp_gid & 255) << 1) + half;

    const float a  = -__expf(Al[d*DS + s]);
    const float dp = Dp[d];
    float h = 0.f;
    const size_t tbase = (size_t)b * KF;

    for (int k = 0; k < KF; ++k) {
        const size_t t = tbase + k;
        float dtv = dt[t*DI + d];
        float xcv = xc[t*DI + d];
        float bm  = dbl[t*48 + 16 + s];
        float cm  = dbl[t*48 + 32 + s];
        h = __expf(dtv * a) * h + dtv * bm * xcv;
        float yp = h * cm;
        yp += __shfl_xor_sync(0xffffffffu, yp, 8);
        yp += __shfl_xor_sync(0xffffffffu, yp, 4);
        yp += __shfl_xor_sync(0xffffffffu, yp, 2);
        yp += __shfl_xor_sync(0xffffffffu, yp, 1);
        if (s == 0) {
            y[t*DI + d] = (yp + dp * xcv) * zs[t*DI + d];
        }
    }
}

// ---------------- masked partial reduction over K ---------------------------
__global__ void reduce_kernel(const float* __restrict__ x,
                              const unsigned char* __restrict__ mask,
                              float* __restrict__ redp)
{
    const int b  = blockIdx.x;
    const int ch = blockIdx.y;
    const int m  = threadIdx.x;
    float acc = 0.f;
    const int kbeg = ch * 64;
    #pragma unroll 4
    for (int k = kbeg; k < kbeg + 64; ++k) {
        if (!mask[b*KF + k])
            acc += x[((size_t)b*KF + k)*DM + m];
    }
    redp[((size_t)b*16 + ch)*DM + m] = acc;
}

// ---------------- combine partials + output projection + mean ---------------
__global__ void final_kernel(const float* __restrict__ redp,
                             const unsigned char* __restrict__ mask,
                             const float* __restrict__ w_op,
                             const float* __restrict__ b_op,
                             float* __restrict__ out)
{
    const int b = blockIdx.x;
    const int o = threadIdx.x;
    __shared__ float s_r[DM];
    __shared__ int s_cnt;

    if (o == 0) s_cnt = 0;
    __syncthreads();

    int c = 0;
    #pragma unroll 4
    for (int k = o; k < KF; k += 256) c += mask[b*KF + k] ? 0 : 1;
    atomicAdd(&s_cnt, c);

    float acc = 0.f;
    #pragma unroll
    for (int ch = 0; ch < 16; ++ch) acc += redp[((size_t)b*16 + ch)*DM + o];
    s_r[o] = acc;
    __syncthreads();

    float cnt = fmaxf((float)s_cnt, 1.0f);
    float dot = 0.f;
    #pragma unroll 4
    for (int m = 0; m < DM; ++m) dot += s_r[m] * w_op[o*DM + m];
    out[(size_t)b*DOUT + o] = dot / cnt + b_op[o];
}

// ---------------- launch ----------------------------------------------------
extern "C" void kernel_launch(void* const* d_in, const int* in_sizes, int n_in,
                              void* d_out, int out_size)
{
    const float*         feats  = (const float*)d_in[0];
    const int*           idx    = (const int*)d_in[1];
    const unsigned char* mask   = (const unsigned char*)d_in[2];
    const float* w_ip   = (const float*)d_in[3];
    const float* b_ip   = (const float*)d_in[4];
    const float* ln_g   = (const float*)d_in[5];
    const float* ln_b   = (const float*)d_in[6];
    const float* W_in   = (const float*)d_in[7];
    const float* conv_w = (const float*)d_in[8];
    const float* conv_b = (const float*)d_in[9];
    const float* W_xp   = (const float*)d_in[10];
    const float* W_dt   = (const float*)d_in[11];
    const float* b_dt   = (const float*)d_in[12];
    const float* A_log  = (const float*)d_in[13];
    const float* Dp     = (const float*)d_in[14];
    const float* W_out  = (const float*)d_in[15];
    const float* w_op   = (const float*)d_in[16];
    const float* b_op   = (const float*)d_in[17];
    float* out = (float*)d_out;

    float *x, *xn, *xz, *xc, *zs, *dbl, *dt, *y, *redp;
    cudaGetSymbolAddress((void**)&x,    g_x);
    cudaGetSymbolAddress((void**)&xn,   g_xn);
    cudaGetSymbolAddress((void**)&xz,   g_xz);
    cudaGetSymbolAddress((void**)&xc,   g_xc);
    cudaGetSymbolAddress((void**)&zs,   g_zs);
    cudaGetSymbolAddress((void**)&dbl,  g_dbl);
    cudaGetSymbolAddress((void**)&dt,   g_dt);
    cudaGetSymbolAddress((void**)&y,    g_y);
    cudaGetSymbolAddress((void**)&redp, g_redp);

    // dynamic smem: 3 stages * (128 + NTILE) * 36 floats
    const int S128 = 3 * (128*36 + 128*36) * 4;   // 110592
    const int S48  = 3 * (128*36 +  48*36) * 4;   // 76032

    cudaFuncSetAttribute(gemm_cp<128, 4, true,  true,  false>,
        cudaFuncAttributeMaxDynamicSharedMemorySize, S128);
    cudaFuncSetAttribute(gemm_cp<128, 4, false, false, false>,
        cudaFuncAttributeMaxDynamicSharedMemorySize, S128);
    cudaFuncSetAttribute(gemm_cp<48,  1, false, false, false>,
        cudaFuncAttributeMaxDynamicSharedMemorySize, S48);
    cudaFuncSetAttribute(gemm_cp<128, 4, false, false, true>,
        cudaFuncAttributeMaxDynamicSharedMemorySize, S128);

    // input projection with fused keyframe gather
    gemm_cp<128, 4, true, true, false><<<dim3(DM/128, NT/128), 256, S128>>>(
        nullptr, w_ip, x, DM, DIN, b_ip, nullptr, feats, idx);

    for (int l = 0; l < NL; ++l) {
        ln_kernel<<<NT, 256>>>(x, ln_g + l*DM, ln_b + l*DM, xn);

        // xz = xn @ W_in^T
        gemm_cp<128, 4, false, false, false>
            <<<dim3(2*DI/128, NT/128), 256, S128>>>(
            xn, W_in + (size_t)l*2*DI*DM, xz, 2*DI, DM,
            nullptr, nullptr, nullptr, nullptr);

        conv_zs_kernel<<<(NT*DI/4)/256, 256>>>(
            xz, conv_w + (size_t)l*DI*DCONV, conv_b + (size_t)l*DI, xc, zs);

        // dbl = xc @ W_xp^T  (dt_low | Bm | Cm), N=48
        gemm_cp<48, 1, false, false, false>
            <<<dim3(1, NT/128), 256, S48>>>(
            xc, W_xp + (size_t)l*(DTR+2*DS)*DI, dbl, 48, DI,
            nullptr, nullptr, nullptr, nullptr);

        // dt = softplus(dbl[:, :16] @ W_dt^T + b_dt)
        dt_kernel<<<NT/64, 256>>>(
            dbl, W_dt + (size_t)l*DI*DTR, b_dt + (size_t)l*DI, dt);

        scan_kernel<<<(B_*DI/2)/8, 256>>>(
            dt, xc, dbl, zs, A_log + (size_t)l*DI*DS, Dp + (size_t)l*DI, y);

        // x = y @ W_out^T + x
        gemm_cp<128, 4, false, false, true>
            <<<dim3(DM/128, NT/128), 256, S128>>>(
            y, W_out + (size_t)l*DM*DI, x, DM, DI,
            nullptr, x, nullptr, nullptr);
    }

    reduce_kernel<<<dim3(B_, 16), 256>>>(x, mask, redp);
    final_kernel<<<B_, 256>>>(redp, mask, w_op, b_op, out);
}

// round 5
// speedup vs baseline: 2.4881x; 1.0932x over previous
#include <cuda_runtime.h>
#include <cuda_bf16.h>
#include <math.h>
#include <cstdint>

// Problem constants
#define B_     16
#define T_     4096
#define KF     1024
#define DIN    512
#define DM     256
#define DOUT   256
#define NL     2
#define DS     16
#define DCONV  4
#define DI     512
#define DTR    16
#define NT     (B_*KF)   // 16384 tokens

// ---------------- scratch (device globals; no runtime alloc) ----------------
__device__ float g_x  [(size_t)NT*DM];       // residual stream
__device__ float g_xn [(size_t)NT*DM];       // layernorm output
__device__ float g_xz [(size_t)NT*2*DI];     // in-projection (xp | z)
__device__ float g_xc [(size_t)NT*DI];       // conv+silu output
__device__ float g_dbl[(size_t)NT*48];       // dt_low(16) | Bm(16) | Cm(16)
__device__ float g_dt [(size_t)NT*DI];       // softplus(dt)
__device__ float g_y  [(size_t)NT*DI];       // scan output (gated)
__device__ float g_redp[(size_t)B_*16*DM];   // partial masked sums

// ---------------------------- helpers ---------------------------------------
__device__ __forceinline__ uint32_t f32_to_tf32(float f) {
    uint32_t r;
    asm("cvt.rna.tf32.f32 %0, %1;" : "=r"(r) : "f"(f));
    return r;
}

__device__ __forceinline__ void mma_tf32(float* d, const uint32_t* a,
                                         const uint32_t* b) {
    asm volatile(
        "mma.sync.aligned.m16n8k8.row.col.f32.tf32.tf32.f32 "
        "{%0,%1,%2,%3}, {%4,%5,%6,%7}, {%8,%9}, {%0,%1,%2,%3};"
        : "+f"(d[0]), "+f"(d[1]), "+f"(d[2]), "+f"(d[3])
        : "r"(a[0]), "r"(a[1]), "r"(a[2]), "r"(a[3]),
          "r"(b[0]), "r"(b[1]));
}

#define CP_ASYNC16(smem_u32, gptr) \
    asm volatile("cp.async.ca.shared.global [%0], [%1], 16;" \
        :: "r"(smem_u32), "l"(gptr))
#define CP_COMMIT() asm volatile("cp.async.commit_group;")
#define CP_WAIT(n)  asm volatile("cp.async.wait_group %0;" :: "n"(n))

// =================== cp.async pipelined tf32 GEMM: C = A @ W^T ==============
template<int NTILE, int WN, bool GATHER, bool BIAS, bool RESID>
__global__ __launch_bounds__(256)
void gemm_cp(const float* __restrict__ A, const float* __restrict__ W,
             float* __restrict__ C, int N, int Kd,
             const float* __restrict__ bias, const float* __restrict__ resid,
             const float* __restrict__ feats, const int* __restrict__ idx)
{
    constexpr int STAGES = 3;
    constexpr int WM   = 8 / WN;
    constexpr int RM   = 128 / WM;
    constexpr int RN   = NTILE / WN;
    constexpr int mM   = RM / 16;
    constexpr int mN   = RN / 8;
    constexpr int SA   = 36;
    constexpr int ABUF = 128 * SA;
    constexpr int BBUF = NTILE * SA;
    constexpr int BL   = (NTILE * 8 + 255) / 256;

    extern __shared__ float sm[];
    float* sA = sm;
    float* sB = sm + STAGES * ABUF;
    __shared__ int rowoff[128];

    const int tid  = threadIdx.x;
    const int warp = tid >> 5, lane = tid & 31;
    const int gid  = lane >> 2, tig = lane & 3;
    const int wm   = warp % WM, wn = warp / WM;
    const int m0   = blockIdx.y * 128, n0 = blockIdx.x * NTILE;

    if (GATHER) {
        if (tid < 128) {
            int t = m0 + tid;
            rowoff[tid] = (t >> 10) * T_ + idx[t];
        }
        __syncthreads();
    }

    const uint32_t sAu = (uint32_t)__cvta_generic_to_shared(sA);
    const uint32_t sBu = (uint32_t)__cvta_generic_to_shared(sB);

    auto issue_load = [&](int stage, int k0) {
        const uint32_t as = sAu + (uint32_t)stage * ABUF * 4;
        const uint32_t bs = sBu + (uint32_t)stage * BBUF * 4;
        #pragma unroll
        for (int j = 0; j < 4; ++j) {
            int it = tid + 256 * j;
            int r = it >> 3, q = it & 7;
            const float* p = GATHER
                ? feats + (size_t)rowoff[r] * Kd + k0 + q * 4
                : A + (size_t)(m0 + r) * Kd + k0 + q * 4;
            CP_ASYNC16(as + (uint32_t)(r * SA + q * 4) * 4, p);
        }
        #pragma unroll
        for (int j = 0; j < BL; ++j) {
            int it = tid + 256 * j;
            if ((NTILE * 8 % 256 == 0) || it < NTILE * 8) {
                int r = it >> 3, q = it & 7;
                CP_ASYNC16(bs + (uint32_t)(r * SA + q * 4) * 4,
                           W + (size_t)(n0 + r) * Kd + k0 + q * 4);
            }
        }
    };

    float acc[mM][mN][4];
    #pragma unroll
    for (int i = 0; i < mM; ++i)
        #pragma unroll
        for (int j = 0; j < mN; ++j)
            #pragma unroll
            for (int q = 0; q < 4; ++q) acc[i][j][q] = 0.f;

    const int nc = Kd >> 5;

    #pragma unroll
    for (int s = 0; s < STAGES - 1; ++s) {
        if (s < nc) issue_load(s, s << 5);
        CP_COMMIT();
    }

    for (int i = 0; i < nc; ++i) {
        CP_WAIT(STAGES - 2);
        __syncthreads();

        const int pre = i + STAGES - 1;
        if (pre < nc) issue_load(pre % STAGES, pre << 5);
        CP_COMMIT();

        const float* bA = sA + (i % STAGES) * ABUF;
        const float* bB = sB + (i % STAGES) * BBUF;
        #pragma unroll
        for (int kk = 0; kk < 32; kk += 8) {
            uint32_t afr[mM][4];
            #pragma unroll
            for (int i2 = 0; i2 < mM; ++i2) {
                int rb = wm * RM + i2 * 16;
                afr[i2][0] = f32_to_tf32(bA[(rb + gid)     * SA + kk + tig]);
                afr[i2][1] = f32_to_tf32(bA[(rb + 8 + gid) * SA + kk + tig]);
                afr[i2][2] = f32_to_tf32(bA[(rb + gid)     * SA + kk + tig + 4]);
                afr[i2][3] = f32_to_tf32(bA[(rb + 8 + gid) * SA + kk + tig + 4]);
            }
            uint32_t bfr[mN][2];
            #pragma unroll
            for (int j2 = 0; j2 < mN; ++j2) {
                int cb = wn * RN + j2 * 8;
                bfr[j2][0] = f32_to_tf32(bB[(cb + gid) * SA + kk + tig]);
                bfr[j2][1] = f32_to_tf32(bB[(cb + gid) * SA + kk + tig + 4]);
            }
            #pragma unroll
            for (int i2 = 0; i2 < mM; ++i2)
                #pragma unroll
                for (int j2 = 0; j2 < mN; ++j2)
                    mma_tf32(acc[i2][j2], afr[i2], bfr[j2]);
        }
    }

    #pragma unroll
    for (int i2 = 0; i2 < mM; ++i2) {
        #pragma unroll
        for (int j2 = 0; j2 < mN; ++j2) {
            int row = m0 + wm * RM + i2 * 16 + gid;
            int col = n0 + wn * RN + j2 * 8 + tig * 2;
            float v0 = acc[i2][j2][0], v1 = acc[i2][j2][1];
            float v2 = acc[i2][j2][2], v3 = acc[i2][j2][3];
            if (BIAS) {
                float bc0 = bias[col], bc1 = bias[col + 1];
                v0 += bc0; v1 += bc1; v2 += bc0; v3 += bc1;
            }
            if (RESID) {
                v0 += resid[(size_t)row * N + col];
                v1 += resid[(size_t)row * N + col + 1];
                v2 += resid[(size_t)(row + 8) * N + col];
                v3 += resid[(size_t)(row + 8) * N + col + 1];
            }
            *reinterpret_cast<float2*>(&C[(size_t)row * N + col]) =
                make_float2(v0, v1);
            *reinterpret_cast<float2*>(&C[(size_t)(row + 8) * N + col]) =
                make_float2(v2, v3);
        }
    }
}

// ---------------- LayerNorm over DM=256 (one block per token) ---------------
__global__ void ln_kernel(const float* __restrict__ x,
                          const float* __restrict__ gam,
                          const float* __restrict__ bet,
                          float* __restrict__ xn)
{
    const int t   = blockIdx.x;
    const int tid = threadIdx.x;  // 256
    float v = x[(size_t)t*DM + tid];

    __shared__ float sred[8];

    float s = v;
    #pragma unroll
    for (int o = 16; o; o >>= 1) s += __shfl_xor_sync(0xffffffffu, s, o);
    if ((tid & 31) == 0) sred[tid >> 5] = s;
    __syncthreads();
    if (tid < 32) {
        float q = (tid < 8) ? sred[tid] : 0.f;
        #pragma unroll
        for (int o = 4; o; o >>= 1) q += __shfl_xor_sync(0xffffffffu, q, o);
        if (tid == 0) sred[0] = q;
    }
    __syncthreads();
    float mu = sred[0] * (1.0f / DM);
    __syncthreads();

    float dv = v - mu;
    s = dv * dv;
    #pragma unroll
    for (int o = 16; o; o >>= 1) s += __shfl_xor_sync(0xffffffffu, s, o);
    if ((tid & 31) == 0) sred[tid >> 5] = s;
    __syncthreads();
    if (tid < 32) {
        float q = (tid < 8) ? sred[tid] : 0.f;
        #pragma unroll
        for (int o = 4; o; o >>= 1) q += __shfl_xor_sync(0xffffffffu, q, o);
        if (tid == 0) sred[0] = q;
    }
    __syncthreads();
    float var = sred[0] * (1.0f / DM);

    xn[(size_t)t*DM + tid] = dv * rsqrtf(var + 1e-5f) * gam[tid] + bet[tid];
}

// ------- causal depthwise conv (width 4) + SiLU, 2 timesteps per thread -----
__global__ void conv_kernel(const float* __restrict__ xz,
                            const float* __restrict__ cw,
                            const float* __restrict__ cb,
                            float* __restrict__ xc)
{
    int gi = blockIdx.x * 256 + threadIdx.x;  // over (NT/2)*(DI/4)
    if (gi >= (NT/2)*(DI/4)) return;
    int d4 = (gi & 127) << 2;     // channel base (multiple of 4)
    int th = gi >> 7;             // t-pair index
    int t0 = th << 1;
    int k0 = t0 & (KF-1);

    float4 w0 = *reinterpret_cast<const float4*>(cw + (d4+0)*4);
    float4 w1 = *reinterpret_cast<const float4*>(cw + (d4+1)*4);
    float4 w2 = *reinterpret_cast<const float4*>(cw + (d4+2)*4);
    float4 w3 = *reinterpret_cast<const float4*>(cw + (d4+3)*4);
    const float wj[4][4] = {
        {w0.x, w1.x, w2.x, w3.x},
        {w0.y, w1.y, w2.y, w3.y},
        {w0.z, w1.z, w2.z, w3.z},
        {w0.w, w1.w, w2.w, w3.w}};
    float4 bias4 = *reinterpret_cast<const float4*>(cb + d4);

    float4 tap[5];
    #pragma unroll
    for (int j = 0; j < 5; ++j) {
        int kk = k0 - 3 + j;
        if (kk >= 0)
            tap[j] = *reinterpret_cast<const float4*>(
                xz + (size_t)(t0 - 3 + j) * (2*DI) + d4);
        else
            tap[j] = make_float4(0.f, 0.f, 0.f, 0.f);
    }

    float4 a0 = bias4, a1 = bias4;
    #pragma unroll
    for (int j = 0; j < 4; ++j) {
        a0.x += wj[j][0] * tap[j].x;   a1.x += wj[j][0] * tap[j+1].x;
        a0.y += wj[j][1] * tap[j].y;   a1.y += wj[j][1] * tap[j+1].y;
        a0.z += wj[j][2] * tap[j].z;   a1.z += wj[j][2] * tap[j+1].z;
        a0.w += wj[j][3] * tap[j].w;   a1.w += wj[j][3] * tap[j+1].w;
    }
    float4 o0, o1;
    o0.x = a0.x / (1.f + __expf(-a0.x));  o1.x = a1.x / (1.f + __expf(-a1.x));
    o0.y = a0.y / (1.f + __expf(-a0.y));  o1.y = a1.y / (1.f + __expf(-a1.y));
    o0.z = a0.z / (1.f + __expf(-a0.z));  o1.z = a1.z / (1.f + __expf(-a1.z));
    o0.w = a0.w / (1.f + __expf(-a0.w));  o1.w = a1.w / (1.f + __expf(-a1.w));
    *reinterpret_cast<float4*>(xc + (size_t)t0*DI + d4)       = o0;
    *reinterpret_cast<float4*>(xc + (size_t)(t0+1)*DI + d4)   = o1;
}

// ------- dt = softplus(dbl[:, :16] @ W_dt^T + b_dt), W_dt reg-cached ---------
__global__ void dt_kernel(const float* __restrict__ dbl,
                          const float* __restrict__ Wdt,
                          const float* __restrict__ bdt,
                          float* __restrict__ dtout)
{
    __shared__ float s_dbl[64 * 16];
    const int tid = threadIdx.x;      // 256
    const int t0  = blockIdx.x * 64;

    float w0[16], w1[16];
    #pragma unroll
    for (int r = 0; r < 16; ++r) {
        w0[r] = Wdt[tid * 16 + r];
        w1[r] = Wdt[(tid + 256) * 16 + r];
    }
    const float b0 = bdt[tid], b1 = bdt[tid + 256];

    for (int i = tid; i < 64 * 16; i += 256) {
        int tt = i >> 4, r = i & 15;
        s_dbl[i] = dbl[(size_t)(t0 + tt) * 48 + r];
    }
    __syncthreads();

    for (int tt = 0; tt < 64; ++tt) {
        float a0 = b0, a1 = b1;
        #pragma unroll
        for (int r = 0; r < 16; ++r) {
            float v = s_dbl[tt * 16 + r];
            a0 += v * w0[r];
            a1 += v * w1[r];
        }
        size_t t = (size_t)(t0 + tt) * DI;
        dtout[t + tid]       = (a0 > 20.f) ? a0 : __logf(1.f + __expf(a0));
        dtout[t + tid + 256] = (a1 > 20.f) ? a1 : __logf(1.f + __expf(a1));
    }
}

// -------- selective scan: 4 lanes per d (lane quad = 4 states) ---------------
// warp covers 8 consecutive d's; dt/xc/z/y accesses are 1 sector per warp-iter.
// dA computed as powers of E=exp(-dt) when A == -(s+1) (runtime-verified),
// falling back to per-state exp otherwise.
__global__ void scan_kernel(const float* __restrict__ dt,
                            const float* __restrict__ xc,
                            const float* __restrict__ dbl,
                            const float* __restrict__ xz,
                            const float* __restrict__ Al,
                            const float* __restrict__ Dp,
                            float* __restrict__ y)
{
    const int warp_gid = (blockIdx.x * blockDim.x + threadIdx.x) >> 5; // 0..1023
    const int lane = threadIdx.x & 31;
    const int g = lane >> 2;      // d index within warp (0..7)
    const int q = lane & 3;       // state quad (states 4q..4q+3)
    const int b = warp_gid >> 6;
    const int d = ((warp_gid & 63) << 3) + g;

    const float a0 = -__expf(Al[d*DS + 4*q + 0]);
    const float a1 = -__expf(Al[d*DS + 4*q + 1]);
    const float a2 = -__expf(Al[d*DS + 4*q + 2]);
    const float a3 = -__expf(Al[d*DS + 4*q + 3]);
    const float dp = Dp[d];

    // fast path valid iff a_j == -(4q+j+1) to ~1e-4 relative
    bool fastl = fabsf(a0 + (float)(4*q+1)) < 1e-4f * (4*q+1)
              && fabsf(a1 + (float)(4*q+2)) < 1e-4f * (4*q+2)
              && fabsf(a2 + (float)(4*q+3)) < 1e-4f * (4*q+3)
              && fabsf(a3 + (float)(4*q+4)) < 1e-4f * (4*q+4);
    const bool fast = __all_sync(0xffffffffu, fastl);

    float h0=0.f, h1=0.f, h2=0.f, h3=0.f;
    const size_t tb = (size_t)b * KF;

    // prefetch k=0
    float dtv = dt[tb*DI + d];
    float xcv = xc[tb*DI + d];
    float zv  = xz[tb*(2*DI) + DI + d];
    float4 bm = *reinterpret_cast<const float4*>(dbl + tb*48 + 16 + 4*q);
    float4 cm = *reinterpret_cast<const float4*>(dbl + tb*48 + 32 + 4*q);

    for (int k = 0; k < KF; ++k) {
        // prefetch k+1 (clamped; last iter re-reads current row)
        const size_t tn = tb + ((k < KF-1) ? k+1 : k);
        float  dtv_n = dt[tn*DI + d];
        float  xcv_n = xc[tn*DI + d];
        float  zv_n  = xz[tn*(2*DI) + DI + d];
        float4 bm_n  = *reinterpret_cast<const float4*>(dbl + tn*48 + 16 + 4*q);
        float4 cm_n  = *reinterpret_cast<const float4*>(dbl + tn*48 + 32 + 4*q);

        float p0, p1, p2, p3;
        if (fast) {
            float E  = __expf(-dtv);
            float E2 = E*E, E4 = E2*E2, E8 = E4*E4;
            float base = (q == 0) ? 1.f : (q == 1) ? E4 : (q == 2) ? E8 : E8*E4;
            p0 = base * E;
            p1 = base * E2;
            p2 = p1 * E;
            p3 = base * E4;
        } else {
            p0 = __expf(dtv*a0);
            p1 = __expf(dtv*a1);
            p2 = __expf(dtv*a2);
            p3 = __expf(dtv*a3);
        }
        const float dtx = dtv * xcv;
        h0 = p0*h0 + dtx*bm.x;
        h1 = p1*h1 + dtx*bm.y;
        h2 = p2*h2 + dtx*bm.z;
        h3 = p3*h3 + dtx*bm.w;
        float yp = h0*cm.x + h1*cm.y + h2*cm.z + h3*cm.w;
        yp += __shfl_xor_sync(0xffffffffu, yp, 1);
        yp += __shfl_xor_sync(0xffffffffu, yp, 2);
        if (q == 0) {
            float zs = zv / (1.f + __expf(-zv));
            y[(tb + k)*DI + d] = (yp + dp*xcv) * zs;
        }
        dtv = dtv_n; xcv = xcv_n; zv = zv_n; bm = bm_n; cm = cm_n;
    }
}

// ---------------- masked partial reduction over K ---------------------------
__global__ void reduce_kernel(const float* __restrict__ x,
                              const unsigned char* __restrict__ mask,
                              float* __restrict__ redp)
{
    const int b  = blockIdx.x;
    const int ch = blockIdx.y;
    const int m  = threadIdx.x;
    float acc = 0.f;
    const int kbeg = ch * 64;
    #pragma unroll 4
    for (int k = kbeg; k < kbeg + 64; ++k) {
        if (!mask[b*KF + k])
            acc += x[((size_t)b*KF + k)*DM + m];
    }
    redp[((size_t)b*16 + ch)*DM + m] = acc;
}

// ---------------- combine partials + output projection + mean ---------------
__global__ void final_kernel(const float* __restrict__ redp,
                             const unsigned char* __restrict__ mask,
                             const float* __restrict__ w_op,
                             const float* __restrict__ b_op,
                             float* __restrict__ out)
{
    const int b = blockIdx.x;
    const int o = threadIdx.x;
    __shared__ float s_r[DM];
    __shared__ int s_cnt;

    if (o == 0) s_cnt = 0;
    __syncthreads();

    int c = 0;
    #pragma unroll 4
    for (int k = o; k < KF; k += 256) c += mask[b*KF + k] ? 0 : 1;
    atomicAdd(&s_cnt, c);

    float acc = 0.f;
    #pragma unroll
    for (int ch = 0; ch < 16; ++ch) acc += redp[((size_t)b*16 + ch)*DM + o];
    s_r[o] = acc;
    __syncthreads();

    float cnt = fmaxf((float)s_cnt, 1.0f);
    float dot = 0.f;
    #pragma unroll 4
    for (int m = 0; m < DM; ++m) dot += s_r[m] * w_op[o*DM + m];
    out[(size_t)b*DOUT + o] = dot / cnt + b_op[o];
}

// ---------------- launch ----------------------------------------------------
extern "C" void kernel_launch(void* const* d_in, const int* in_sizes, int n_in,
                              void* d_out, int out_size)
{
    const float*         feats  = (const float*)d_in[0];
    const int*           idx    = (const int*)d_in[1];
    const unsigned char* mask   = (const unsigned char*)d_in[2];
    const float* w_ip   = (const float*)d_in[3];
    const float* b_ip   = (const float*)d_in[4];
    const float* ln_g   = (const float*)d_in[5];
    const float* ln_b   = (const float*)d_in[6];
    const float* W_in   = (const float*)d_in[7];
    const float* conv_w = (const float*)d_in[8];
    const float* conv_b = (const float*)d_in[9];
    const float* W_xp   = (const float*)d_in[10];
    const float* W_dt   = (const float*)d_in[11];
    const float* b_dt   = (const float*)d_in[12];
    const float* A_log  = (const float*)d_in[13];
    const float* Dp     = (const float*)d_in[14];
    const float* W_out  = (const float*)d_in[15];
    const float* w_op   = (const float*)d_in[16];
    const float* b_op   = (const float*)d_in[17];
    float* out = (float*)d_out;

    float *x, *xn, *xz, *xc, *dbl, *dt, *y, *redp;
    cudaGetSymbolAddress((void**)&x,    g_x);
    cudaGetSymbolAddress((void**)&xn,   g_xn);
    cudaGetSymbolAddress((void**)&xz,   g_xz);
    cudaGetSymbolAddress((void**)&xc,   g_xc);
    cudaGetSymbolAddress((void**)&dbl,  g_dbl);
    cudaGetSymbolAddress((void**)&dt,   g_dt);
    cudaGetSymbolAddress((void**)&y,    g_y);
    cudaGetSymbolAddress((void**)&redp, g_redp);

    const int S128 = 3 * (128*36 + 128*36) * 4;   // 110592
    const int S48  = 3 * (128*36 +  48*36) * 4;   // 76032

    cudaFuncSetAttribute(gemm_cp<128, 4, true,  true,  false>,
        cudaFuncAttributeMaxDynamicSharedMemorySize, S128);
    cudaFuncSetAttribute(gemm_cp<128, 4, false, false, false>,
        cudaFuncAttributeMaxDynamicSharedMemorySize, S128);
    cudaFuncSetAttribute(gemm_cp<48,  1, false, false, false>,
        cudaFuncAttributeMaxDynamicSharedMemorySize, S48);
    cudaFuncSetAttribute(gemm_cp<128, 4, false, false, true>,
        cudaFuncAttributeMaxDynamicSharedMemorySize, S128);

    // input projection with fused keyframe gather
    gemm_cp<128, 4, true, true, false><<<dim3(DM/128, NT/128), 256, S128>>>(
        nullptr, w_ip, x, DM, DIN, b_ip, nullptr, feats, idx);

    for (int l = 0; l < NL; ++l) {
        ln_kernel<<<NT, 256>>>(x, ln_g + l*DM, ln_b + l*DM, xn);

        // xz = xn @ W_in^T
        gemm_cp<128, 4, false, false, false>
            <<<dim3(2*DI/128, NT/128), 256, S128>>>(
            xn, W_in + (size_t)l*2*DI*DM, xz, 2*DI, DM,
            nullptr, nullptr, nullptr, nullptr);

        conv_kernel<<<((NT/2)*(DI/4))/256, 256>>>(
            xz, conv_w + (size_t)l*DI*DCONV, conv_b + (size_t)l*DI, xc);

        // dbl = xc @ W_xp^T  (dt_low | Bm | Cm), N=48
        gemm_cp<48, 1, false, false, false>
            <<<dim3(1, NT/128), 256, S48>>>(
            xc, W_xp + (size_t)l*(DTR+2*DS)*DI, dbl, 48, DI,
            nullptr, nullptr, nullptr, nullptr);

        // dt = softplus(dbl[:, :16] @ W_dt^T + b_dt)
        dt_kernel<<<NT/64, 256>>>(
            dbl, W_dt + (size_t)l*DI*DTR, b_dt + (size_t)l*DI, dt);

        // scan: 1024 warps = 128 blocks x 256 threads
        scan_kernel<<<128, 256>>>(
            dt, xc, dbl, xz, A_log + (size_t)l*DI*DS, Dp + (size_t)l*DI, y);

        // x = y @ W_out^T + x
        gemm_cp<128, 4, false, false, true>
            <<<dim3(DM/128, NT/128), 256, S128>>>(
            y, W_out + (size_t)l*DM*DI, x, DM, DI,
            nullptr, x, nullptr, nullptr);
    }

    reduce_kernel<<<dim3(B_, 16), 256>>>(x, mask, redp);
    final_kernel<<<B_, 256>>>(redp, mask, w_op, b_op, out);
}

// round 6
// speedup vs baseline: 2.6204x; 1.0532x over previous
#include <cuda_runtime.h>
#include <cuda_fp16.h>
#include <math.h>
#include <cstdint>

// Problem constants
#define B_     16
#define T_     4096
#define KF     1024
#define DIN    512
#define DM     256
#define DOUT   256
#define NL     2
#define DS     16
#define DCONV  4
#define DI     512
#define DTR    16
#define NT     (B_*KF)   // 16384 tokens

// ---------------- scratch (device globals; no runtime alloc) ----------------
__device__ float g_x  [(size_t)NT*DM];       // residual stream
__device__ float g_xn [(size_t)NT*DM];       // layernorm output
__device__ float g_xz [(size_t)NT*2*DI];     // in-projection (xp | z)
__device__ float g_xc [(size_t)NT*DI];       // conv+silu output
__device__ float g_dbl[(size_t)NT*48];       // dt_low(16) | Bm(16) | Cm(16)
__device__ float g_dt [(size_t)NT*DI];       // softplus(dt)
__device__ float g_y  [(size_t)NT*DI];       // scan output (gated)
__device__ float g_redp[(size_t)B_*16*DM];   // partial masked sums

// ---------------------------- helpers ---------------------------------------
__device__ __forceinline__ void mma_fp16(float* d, const uint32_t* a,
                                         const uint32_t* b) {
    asm volatile(
        "mma.sync.aligned.m16n8k16.row.col.f32.f16.f16.f32 "
        "{%0,%1,%2,%3}, {%4,%5,%6,%7}, {%8,%9}, {%0,%1,%2,%3};"
        : "+f"(d[0]), "+f"(d[1]), "+f"(d[2]), "+f"(d[3])
        : "r"(a[0]), "r"(a[1]), "r"(a[2]), "r"(a[3]),
          "r"(b[0]), "r"(b[1]));
}

__device__ __forceinline__ uint32_t pack_half2(float lo, float hi) {
    __half2 h = __floats2half2_rn(lo, hi);
    return *reinterpret_cast<uint32_t*>(&h);
}

// =================== fp16 mma.sync GEMM: C = A @ W^T ========================
// CTA tile 128 x NTILE, 8 warps (WM x WN), K chunked by 32 f32.
// f32 inputs converted to fp16 on the smem-store path; fp32 accumulate.
// Smem rows padded to 40 halves (conflict-free for k16 fragment loads).
template<int NTILE, int WN, bool GATHER, bool BIAS, bool RESID>
__global__ __launch_bounds__(256, 2)
void gemm_fp16(const float* __restrict__ A, const float* __restrict__ W,
               float* __restrict__ C, int N, int Kd,
               const float* __restrict__ bias, const float* __restrict__ resid,
               const float* __restrict__ feats, const int* __restrict__ idx)
{
    constexpr int WM = 8 / WN;
    constexpr int RM = 128 / WM;
    constexpr int RN = NTILE / WN;
    constexpr int mM = RM / 16;
    constexpr int mN = RN / 8;
    constexpr int SA = 40;                       // halves per row (80 B)
    constexpr int BL = (NTILE * 8 + 255) / 256;  // B float4 loads per thread

    __shared__ __half sA[2][128 * SA];
    __shared__ __half sB[2][NTILE * SA];
    __shared__ int rowoff[128];

    const int tid  = threadIdx.x;
    const int warp = tid >> 5, lane = tid & 31;
    const int g    = lane >> 2, t = lane & 3;
    const int wm   = warp % WM, wn = warp / WM;
    const int m0   = blockIdx.y * 128, n0 = blockIdx.x * NTILE;

    if (GATHER) {
        if (tid < 128) {
            int tok = m0 + tid;
            rowoff[tid] = (tok >> 10) * T_ + idx[tok];
        }
        __syncthreads();
    }

    float4 ar[4];
    float4 br[BL];

    auto ldA = [&](int k0) {
        #pragma unroll
        for (int j = 0; j < 4; ++j) {
            int it = tid + 256 * j;
            int r = it >> 3, q = it & 7;
            const float* p = GATHER
                ? feats + (size_t)rowoff[r] * Kd + k0 + q * 4
                : A + (size_t)(m0 + r) * Kd + k0 + q * 4;
            ar[j] = *reinterpret_cast<const float4*>(p);
        }
    };
    auto ldB = [&](int k0) {
        #pragma unroll
        for (int j = 0; j < BL; ++j) {
            int it = tid + 256 * j;
            if ((NTILE * 8 % 256 == 0) || it < NTILE * 8) {
                int r = it >> 3, q = it & 7;
                br[j] = *reinterpret_cast<const float4*>(
                    W + (size_t)(n0 + r) * Kd + k0 + q * 4);
            }
        }
    };
    auto stA = [&](int buf) {
        #pragma unroll
        for (int j = 0; j < 4; ++j) {
            int it = tid + 256 * j;
            int r = it >> 3, q = it & 7;
            uint2 u = make_uint2(pack_half2(ar[j].x, ar[j].y),
                                 pack_half2(ar[j].z, ar[j].w));
            *reinterpret_cast<uint2*>(&sA[buf][r * SA + q * 4]) = u;
        }
    };
    auto stB = [&](int buf) {
        #pragma unroll
        for (int j = 0; j < BL; ++j) {
            int it = tid + 256 * j;
            if ((NTILE * 8 % 256 == 0) || it < NTILE * 8) {
                int r = it >> 3, q = it & 7;
                uint2 u = make_uint2(pack_half2(br[j].x, br[j].y),
                                     pack_half2(br[j].z, br[j].w));
                *reinterpret_cast<uint2*>(&sB[buf][r * SA + q * 4]) = u;
            }
        }
    };

    float acc[mM][mN][4];
    #pragma unroll
    for (int i = 0; i < mM; ++i)
        #pragma unroll
        for (int j = 0; j < mN; ++j)
            #pragma unroll
            for (int q = 0; q < 4; ++q) acc[i][j][q] = 0.f;

    const int nc = Kd >> 5;
    ldA(0); ldB(0);
    stA(0); stB(0);
    __syncthreads();

    for (int i = 0; i < nc; ++i) {
        const int buf = i & 1;
        if (i + 1 < nc) { ldA((i + 1) << 5); ldB((i + 1) << 5); }

        const __half* bA = sA[buf];
        const __half* bB = sB[buf];
        #pragma unroll
        for (int kk = 0; kk < 32; kk += 16) {
            uint32_t afr[mM][4];
            #pragma unroll
            for (int i2 = 0; i2 < mM; ++i2) {
                int rb = wm * RM + i2 * 16;
                afr[i2][0] = *reinterpret_cast<const uint32_t*>(
                    &bA[(rb + g)     * SA + kk + 2*t]);
                afr[i2][1] = *reinterpret_cast<const uint32_t*>(
                    &bA[(rb + 8 + g) * SA + kk + 2*t]);
                afr[i2][2] = *reinterpret_cast<const uint32_t*>(
                    &bA[(rb + g)     * SA + kk + 2*t + 8]);
                afr[i2][3] = *reinterpret_cast<const uint32_t*>(
                    &bA[(rb + 8 + g) * SA + kk + 2*t + 8]);
            }
            uint32_t bfr[mN][2];
            #pragma unroll
            for (int j2 = 0; j2 < mN; ++j2) {
                int cb = wn * RN + j2 * 8;
                bfr[j2][0] = *reinterpret_cast<const uint32_t*>(
                    &bB[(cb + g) * SA + kk + 2*t]);
                bfr[j2][1] = *reinterpret_cast<const uint32_t*>(
                    &bB[(cb + g) * SA + kk + 2*t + 8]);
            }
            #pragma unroll
            for (int i2 = 0; i2 < mM; ++i2)
                #pragma unroll
                for (int j2 = 0; j2 < mN; ++j2)
                    mma_fp16(acc[i2][j2], afr[i2], bfr[j2]);
        }

        if (i + 1 < nc) { stA(buf ^ 1); stB(buf ^ 1); __syncthreads(); }
    }

    // epilogue (same accumulator layout as m16n8k8)
    #pragma unroll
    for (int i2 = 0; i2 < mM; ++i2) {
        #pragma unroll
        for (int j2 = 0; j2 < mN; ++j2) {
            int row = m0 + wm * RM + i2 * 16 + g;
            int col = n0 + wn * RN + j2 * 8 + t * 2;
            float v0 = acc[i2][j2][0], v1 = acc[i2][j2][1];
            float v2 = acc[i2][j2][2], v3 = acc[i2][j2][3];
            if (BIAS) {
                float bc0 = bias[col], bc1 = bias[col + 1];
                v0 += bc0; v1 += bc1; v2 += bc0; v3 += bc1;
            }
            if (RESID) {
                v0 += resid[(size_t)row * N + col];
                v1 += resid[(size_t)row * N + col + 1];
                v2 += resid[(size_t)(row + 8) * N + col];
                v3 += resid[(size_t)(row + 8) * N + col + 1];
            }
            *reinterpret_cast<float2*>(&C[(size_t)row * N + col]) =
                make_float2(v0, v1);
            *reinterpret_cast<float2*>(&C[(size_t)(row + 8) * N + col]) =
                make_float2(v2, v3);
        }
    }
}

// ---------------- LayerNorm over DM=256 (one block per token) ---------------
__global__ void ln_kernel(const float* __restrict__ x,
                          const float* __restrict__ gam,
                          const float* __restrict__ bet,
                          float* __restrict__ xn)
{
    const int t   = blockIdx.x;
    const int tid = threadIdx.x;  // 256
    float v = x[(size_t)t*DM + tid];

    __shared__ float sred[8];

    float s = v;
    #pragma unroll
    for (int o = 16; o; o >>= 1) s += __shfl_xor_sync(0xffffffffu, s, o);
    if ((tid & 31) == 0) sred[tid >> 5] = s;
    __syncthreads();
    if (tid < 32) {
        float q = (tid < 8) ? sred[tid] : 0.f;
        #pragma unroll
        for (int o = 4; o; o >>= 1) q += __shfl_xor_sync(0xffffffffu, q, o);
        if (tid == 0) sred[0] = q;
    }
    __syncthreads();
    float mu = sred[0] * (1.0f / DM);
    __syncthreads();

    float dv = v - mu;
    s = dv * dv;
    #pragma unroll
    for (int o = 16; o; o >>= 1) s += __shfl_xor_sync(0xffffffffu, s, o);
    if ((tid & 31) == 0) sred[tid >> 5] = s;
    __syncthreads();
    if (tid < 32) {
        float q = (tid < 8) ? sred[tid] : 0.f;
        #pragma unroll
        for (int o = 4; o; o >>= 1) q += __shfl_xor_sync(0xffffffffu, q, o);
        if (tid == 0) sred[0] = q;
    }
    __syncthreads();
    float var = sred[0] * (1.0f / DM);

    xn[(size_t)t*DM + tid] = dv * rsqrtf(var + 1e-5f) * gam[tid] + bet[tid];
}

// ------- causal depthwise conv (width 4) + SiLU, 2 timesteps per thread -----
__global__ void conv_kernel(const float* __restrict__ xz,
                            const float* __restrict__ cw,
                            const float* __restrict__ cb,
                            float* __restrict__ xc)
{
    int gi = blockIdx.x * 256 + threadIdx.x;  // over (NT/2)*(DI/4)
    if (gi >= (NT/2)*(DI/4)) return;
    int d4 = (gi & 127) << 2;
    int th = gi >> 7;
    int t0 = th << 1;
    int k0 = t0 & (KF-1);

    float4 w0 = *reinterpret_cast<const float4*>(cw + (d4+0)*4);
    float4 w1 = *reinterpret_cast<const float4*>(cw + (d4+1)*4);
    float4 w2 = *reinterpret_cast<const float4*>(cw + (d4+2)*4);
    float4 w3 = *reinterpret_cast<const float4*>(cw + (d4+3)*4);
    const float wj[4][4] = {
        {w0.x, w1.x, w2.x, w3.x},
        {w0.y, w1.y, w2.y, w3.y},
        {w0.z, w1.z, w2.z, w3.z},
        {w0.w, w1.w, w2.w, w3.w}};
    float4 bias4 = *reinterpret_cast<const float4*>(cb + d4);

    float4 tap[5];
    #pragma unroll
    for (int j = 0; j < 5; ++j) {
        int kk = k0 - 3 + j;
        if (kk >= 0)
            tap[j] = *reinterpret_cast<const float4*>(
                xz + (size_t)(t0 - 3 + j) * (2*DI) + d4);
        else
            tap[j] = make_float4(0.f, 0.f, 0.f, 0.f);
    }

    float4 a0 = bias4, a1 = bias4;
    #pragma unroll
    for (int j = 0; j < 4; ++j) {
        a0.x += wj[j][0] * tap[j].x;   a1.x += wj[j][0] * tap[j+1].x;
        a0.y += wj[j][1] * tap[j].y;   a1.y += wj[j][1] * tap[j+1].y;
        a0.z += wj[j][2] * tap[j].z;   a1.z += wj[j][2] * tap[j+1].z;
        a0.w += wj[j][3] * tap[j].w;   a1.w += wj[j][3] * tap[j+1].w;
    }
    float4 o0, o1;
    o0.x = a0.x / (1.f + __expf(-a0.x));  o1.x = a1.x / (1.f + __expf(-a1.x));
    o0.y = a0.y / (1.f + __expf(-a0.y));  o1.y = a1.y / (1.f + __expf(-a1.y));
    o0.z = a0.z / (1.f + __expf(-a0.z));  o1.z = a1.z / (1.f + __expf(-a1.z));
    o0.w = a0.w / (1.f + __expf(-a0.w));  o1.w = a1.w / (1.f + __expf(-a1.w));
    *reinterpret_cast<float4*>(xc + (size_t)t0*DI + d4)       = o0;
    *reinterpret_cast<float4*>(xc + (size_t)(t0+1)*DI + d4)   = o1;
}

// ------- dt = softplus(dbl[:, :16] @ W_dt^T + b_dt), W_dt reg-cached ---------
__global__ void dt_kernel(const float* __restrict__ dbl,
                          const float* __restrict__ Wdt,
                          const float* __restrict__ bdt,
                          float* __restrict__ dtout)
{
    __shared__ float s_dbl[64 * 16];
    const int tid = threadIdx.x;      // 256
    const int t0  = blockIdx.x * 64;

    float w0[16], w1[16];
    #pragma unroll
    for (int r = 0; r < 16; ++r) {
        w0[r] = Wdt[tid * 16 + r];
        w1[r] = Wdt[(tid + 256) * 16 + r];
    }
    const float b0 = bdt[tid], b1 = bdt[tid + 256];

    for (int i = tid; i < 64 * 16; i += 256) {
        int tt = i >> 4, r = i & 15;
        s_dbl[i] = dbl[(size_t)(t0 + tt) * 48 + r];
    }
    __syncthreads();

    for (int tt = 0; tt < 64; ++tt) {
        float a0 = b0, a1 = b1;
        #pragma unroll
        for (int r = 0; r < 16; ++r) {
            float v = s_dbl[tt * 16 + r];
            a0 += v * w0[r];
            a1 += v * w1[r];
        }
        size_t t = (size_t)(t0 + tt) * DI;
        dtout[t + tid]       = (a0 > 20.f) ? a0 : __logf(1.f + __expf(a0));
        dtout[t + tid + 256] = (a1 > 20.f) ? a1 : __logf(1.f + __expf(a1));
    }
}

// -------- selective scan: 4 lanes per d (lane quad = 4 states) ---------------
__global__ void scan_kernel(const float* __restrict__ dt,
                            const float* __restrict__ xc,
                            const float* __restrict__ dbl,
                            const float* __restrict__ xz,
                            const float* __restrict__ Al,
                            const float* __restrict__ Dp,
                            float* __restrict__ y)
{
    const int warp_gid = (blockIdx.x * blockDim.x + threadIdx.x) >> 5;
    const int lane = threadIdx.x & 31;
    const int g = lane >> 2;
    const int q = lane & 3;
    const int b = warp_gid >> 6;
    const int d = ((warp_gid & 63) << 3) + g;

    const float a0 = -__expf(Al[d*DS + 4*q + 0]);
    const float a1 = -__expf(Al[d*DS + 4*q + 1]);
    const float a2 = -__expf(Al[d*DS + 4*q + 2]);
    const float a3 = -__expf(Al[d*DS + 4*q + 3]);
    const float dp = Dp[d];

    bool fastl = fabsf(a0 + (float)(4*q+1)) < 1e-4f * (4*q+1)
              && fabsf(a1 + (float)(4*q+2)) < 1e-4f * (4*q+2)
              && fabsf(a2 + (float)(4*q+3)) < 1e-4f * (4*q+3)
              && fabsf(a3 + (float)(4*q+4)) < 1e-4f * (4*q+4);
    const bool fast = __all_sync(0xffffffffu, fastl);

    float h0=0.f, h1=0.f, h2=0.f, h3=0.f;
    const size_t tb = (size_t)b * KF;

    float dtv = dt[tb*DI + d];
    float xcv = xc[tb*DI + d];
    float zv  = xz[tb*(2*DI) + DI + d];
    float4 bm = *reinterpret_cast<const float4*>(dbl + tb*48 + 16 + 4*q);
    float4 cm = *reinterpret_cast<const float4*>(dbl + tb*48 + 32 + 4*q);

    for (int k = 0; k < KF; ++k) {
        const size_t tn = tb + ((k < KF-1) ? k+1 : k);
        float  dtv_n = dt[tn*DI + d];
        float  xcv_n = xc[tn*DI + d];
        float  zv_n  = xz[tn*(2*DI) + DI + d];
        float4 bm_n  = *reinterpret_cast<const float4*>(dbl + tn*48 + 16 + 4*q);
        float4 cm_n  = *reinterpret_cast<const float4*>(dbl + tn*48 + 32 + 4*q);

        float p0, p1, p2, p3;
        if (fast) {
            float E  = __expf(-dtv);
            float E2 = E*E, E4 = E2*E2, E8 = E4*E4;
            float base = (q == 0) ? 1.f : (q == 1) ? E4 : (q == 2) ? E8 : E8*E4;
            p0 = base * E;
            p1 = base * E2;
            p2 = p1 * E;
            p3 = base * E4;
        } else {
            p0 = __expf(dtv*a0);
            p1 = __expf(dtv*a1);
            p2 = __expf(dtv*a2);
            p3 = __expf(dtv*a3);
        }
        const float dtx = dtv * xcv;
        h0 = p0*h0 + dtx*bm.x;
        h1 = p1*h1 + dtx*bm.y;
        h2 = p2*h2 + dtx*bm.z;
        h3 = p3*h3 + dtx*bm.w;
        float yp = h0*cm.x + h1*cm.y + h2*cm.z + h3*cm.w;
        yp += __shfl_xor_sync(0xffffffffu, yp, 1);
        yp += __shfl_xor_sync(0xffffffffu, yp, 2);
        if (q == 0) {
            float zs = zv / (1.f + __expf(-zv));
            y[(tb + k)*DI + d] = (yp + dp*xcv) * zs;
        }
        dtv = dtv_n; xcv = xcv_n; zv = zv_n; bm = bm_n; cm = cm_n;
    }
}

// ---------------- masked partial reduction over K ---------------------------
__global__ void reduce_kernel(const float* __restrict__ x,
                              const unsigned char* __restrict__ mask,
                              float* __restrict__ redp)
{
    const int b  = blockIdx.x;
    const int ch = blockIdx.y;
    const int m  = threadIdx.x;
    float acc = 0.f;
    const int kbeg = ch * 64;
    #pragma unroll 4
    for (int k = kbeg; k < kbeg + 64; ++k) {
        if (!mask[b*KF + k])
            acc += x[((size_t)b*KF + k)*DM + m];
    }
    redp[((size_t)b*16 + ch)*DM + m] = acc;
}

// ---------------- combine partials + output projection + mean ---------------
__global__ void final_kernel(const float* __restrict__ redp,
                             const unsigned char* __restrict__ mask,
                             const float* __restrict__ w_op,
                             const float* __restrict__ b_op,
                             float* __restrict__ out)
{
    const int b = blockIdx.x;
    const int o = threadIdx.x;
    __shared__ float s_r[DM];
    __shared__ int s_cnt;

    if (o == 0) s_cnt = 0;
    __syncthreads();

    int c = 0;
    #pragma unroll 4
    for (int k = o; k < KF; k += 256) c += mask[b*KF + k] ? 0 : 1;
    atomicAdd(&s_cnt, c);

    float acc = 0.f;
    #pragma unroll
    for (int ch = 0; ch < 16; ++ch) acc += redp[((size_t)b*16 + ch)*DM + o];
    s_r[o] = acc;
    __syncthreads();

    float cnt = fmaxf((float)s_cnt, 1.0f);
    float dot = 0.f;
    #pragma unroll 4
    for (int m = 0; m < DM; ++m) dot += s_r[m] * w_op[o*DM + m];
    out[(size_t)b*DOUT + o] = dot / cnt + b_op[o];
}

// ---------------- launch ----------------------------------------------------
extern "C" void kernel_launch(void* const* d_in, const int* in_sizes, int n_in,
                              void* d_out, int out_size)
{
    const float*         feats  = (const float*)d_in[0];
    const int*           idx    = (const int*)d_in[1];
    const unsigned char* mask   = (const unsigned char*)d_in[2];
    const float* w_ip   = (const float*)d_in[3];
    const float* b_ip   = (const float*)d_in[4];
    const float* ln_g   = (const float*)d_in[5];
    const float* ln_b   = (const float*)d_in[6];
    const float* W_in   = (const float*)d_in[7];
    const float* conv_w = (const float*)d_in[8];
    const float* conv_b = (const float*)d_in[9];
    const float* W_xp   = (const float*)d_in[10];
    const float* W_dt   = (const float*)d_in[11];
    const float* b_dt   = (const float*)d_in[12];
    const float* A_log  = (const float*)d_in[13];
    const float* Dp     = (const float*)d_in[14];
    const float* W_out  = (const float*)d_in[15];
    const float* w_op   = (const float*)d_in[16];
    const float* b_op   = (const float*)d_in[17];
    float* out = (float*)d_out;

    float *x, *xn, *xz, *xc, *dbl, *dt, *y, *redp;
    cudaGetSymbolAddress((void**)&x,    g_x);
    cudaGetSymbolAddress((void**)&xn,   g_xn);
    cudaGetSymbolAddress((void**)&xz,   g_xz);
    cudaGetSymbolAddress((void**)&xc,   g_xc);
    cudaGetSymbolAddress((void**)&dbl,  g_dbl);
    cudaGetSymbolAddress((void**)&dt,   g_dt);
    cudaGetSymbolAddress((void**)&y,    g_y);
    cudaGetSymbolAddress((void**)&redp, g_redp);

    // input projection with fused keyframe gather
    gemm_fp16<64, 2, true, true, false><<<dim3(DM/64, NT/128), 256>>>(
        nullptr, w_ip, x, DM, DIN, b_ip, nullptr, feats, idx);

    for (int l = 0; l < NL; ++l) {
        ln_kernel<<<NT, 256>>>(x, ln_g + l*DM, ln_b + l*DM, xn);

        // xz = xn @ W_in^T
        gemm_fp16<64, 2, false, false, false>
            <<<dim3(2*DI/64, NT/128), 256>>>(
            xn, W_in + (size_t)l*2*DI*DM, xz, 2*DI, DM,
            nullptr, nullptr, nullptr, nullptr);

        conv_kernel<<<((NT/2)*(DI/4))/256, 256>>>(
            xz, conv_w + (size_t)l*DI*DCONV, conv_b + (size_t)l*DI, xc);

        // dbl = xc @ W_xp^T  (dt_low | Bm | Cm), N=48
        gemm_fp16<48, 1, false, false, false>
            <<<dim3(1, NT/128), 256>>>(
            xc, W_xp + (size_t)l*(DTR+2*DS)*DI, dbl, 48, DI,
            nullptr, nullptr, nullptr, nullptr);

        // dt = softplus(dbl[:, :16] @ W_dt^T + b_dt)
        dt_kernel<<<NT/64, 256>>>(
            dbl, W_dt + (size_t)l*DI*DTR, b_dt + (size_t)l*DI, dt);

        // scan: 1024 warps = 128 blocks x 256 threads
        scan_kernel<<<128, 256>>>(
            dt, xc, dbl, xz, A_log + (size_t)l*DI*DS, Dp + (size_t)l*DI, y);

        // x = y @ W_out^T + x
        gemm_fp16<64, 2, false, false, true>
            <<<dim3(DM/64, NT/128), 256>>>(
            y, W_out + (size_t)l*DM*DI, x, DM, DI,
            nullptr, x, nullptr, nullptr);
    }

    reduce_kernel<<<dim3(B_, 16), 256>>>(x, mask, redp);
    final_kernel<<<B_, 256>>>(redp, mask, w_op, b_op, out);
}